// round 3
// baseline (speedup 1.0000x reference)
#include <cuda_runtime.h>
#include <math.h>

// Problem dims (fixed by reference)
#define BB 256      // batch
#define TT 500      // time steps
#define II 256      // input dim
#define HH 512      // hidden dim
#define GG 2048     // 4*H
#define OO 100      // output dim
#define NBLK 128    // persistent blocks (<= 148 SMs -> all resident)

// Scratch (allocation-free: __device__ globals)
__device__ float g_xg[(size_t)TT * BB * GG];   // [T][B][4H] input projections (+bx+bh)
__device__ float g_hbuf[2][BB * HH];           // double-buffered hidden state
__device__ unsigned g_bar_count;
__device__ volatile unsigned g_epoch;

// ---------------- Tiled GEMM config ----------------
#define Bb 64
#define Bn 64
#define Bk 16

// ---------------- packed f32x2 helpers (sm_103a FFMA2 path) ----------------
__device__ __forceinline__ unsigned long long pk2(float x, float y) {
    unsigned long long r;
    asm("mov.b64 %0, {%1, %2};" : "=l"(r) : "r"(__float_as_uint(x)), "r"(__float_as_uint(y)));
    return r;
}
__device__ __forceinline__ unsigned long long dup2(float x) {
    unsigned long long r;
    asm("mov.b64 %0, {%1, %1};" : "=l"(r) : "r"(__float_as_uint(x)));
    return r;
}
__device__ __forceinline__ void fma2(unsigned long long& d, unsigned long long a,
                                     unsigned long long b) {
    asm("fma.rn.f32x2 %0, %1, %2, %0;" : "+l"(d) : "l"(a), "l"(b));
}
__device__ __forceinline__ float2 upk2(unsigned long long v) {
    float2 f;
    asm("mov.b64 {%0, %1}, %2;" : "=f"(f.x), "=f"(f.y) : "l"(v));
    return f;
}

// ---------------------------------------------------------------------------
// Kernel 1: xg[t][b][g] = sum_i x[b][t][i] * Wx[g][i] + bx[g] + bh[g]
// M = T*B rows (row m -> t = m/256, b = m%256). Grid (2000, 32), 256 thr.
// ---------------------------------------------------------------------------
__global__ __launch_bounds__(256) void xg_gemm(const float* __restrict__ x,
                                               const float* __restrict__ Wx,
                                               const float* __restrict__ bx,
                                               const float* __restrict__ bh) {
    __shared__ __align__(16) float As[Bk][Bb];
    __shared__ __align__(16) float Bs[Bk][Bn];

    const int mBase = blockIdx.x * Bb;
    const int nBase = blockIdx.y * Bn;
    const int t  = mBase >> 8;
    const int b0 = mBase & 255;

    const int tid = threadIdx.x;
    const int tx = tid & 15;
    const int ty = tid >> 4;
    const int lr  = tid >> 2;
    const int lk4 = (tid & 3) << 2;

    const float* Abase = x + (size_t)b0 * TT * II + (size_t)t * II;
    const size_t aRowStride = (size_t)TT * II;

    unsigned long long accp[4][2] = {};

    for (int k0 = 0; k0 < II; k0 += Bk) {
        float4 av = *reinterpret_cast<const float4*>(Abase + (size_t)lr * aRowStride + k0 + lk4);
        float4 bv = *reinterpret_cast<const float4*>(Wx + (size_t)(nBase + lr) * II + k0 + lk4);
        As[lk4 + 0][lr] = av.x; As[lk4 + 1][lr] = av.y;
        As[lk4 + 2][lr] = av.z; As[lk4 + 3][lr] = av.w;
        Bs[lk4 + 0][lr] = bv.x; Bs[lk4 + 1][lr] = bv.y;
        Bs[lk4 + 2][lr] = bv.z; Bs[lk4 + 3][lr] = bv.w;
        __syncthreads();
#pragma unroll
        for (int kk = 0; kk < Bk; kk++) {
            float4 a  = *reinterpret_cast<const float4*>(&As[kk][ty << 2]);
            float4 bb = *reinterpret_cast<const float4*>(&Bs[kk][tx << 2]);
            unsigned long long b0p = pk2(bb.x, bb.y);
            unsigned long long b1p = pk2(bb.z, bb.w);
            float ar[4] = {a.x, a.y, a.z, a.w};
#pragma unroll
            for (int i = 0; i < 4; i++) {
                unsigned long long ai = dup2(ar[i]);
                fma2(accp[i][0], ai, b0p);
                fma2(accp[i][1], ai, b1p);
            }
        }
        __syncthreads();
    }

    // epilogue: + bx + bh, write g_xg
    float biasj[4];
#pragma unroll
    for (int j = 0; j < 4; j++) {
        int n = nBase + (tx << 2) + j;
        biasj[j] = bx[n] + bh[n];
    }
#pragma unroll
    for (int i = 0; i < 4; i++) {
        int m = mBase + (ty << 2) + i;
        float2 p0 = upk2(accp[i][0]);
        float2 p1 = upk2(accp[i][1]);
        float v[4] = {p0.x, p0.y, p1.x, p1.y};
#pragma unroll
        for (int j = 0; j < 4; j++) {
            int n = nBase + (tx << 2) + j;
            g_xg[(size_t)m * GG + n] = v[j] + biasj[j];
        }
    }
}

// ---------------------------------------------------------------------------
// Grid-wide software barrier
// ---------------------------------------------------------------------------
__device__ __forceinline__ void grid_bar(unsigned step) {
    __syncthreads();
    if (threadIdx.x == 0) {
        unsigned arrived = atomicAdd(&g_bar_count, 1);
        if (arrived == NBLK - 1) {
            g_bar_count = 0;
            __threadfence();
            g_epoch = step + 1;
        } else {
            while (g_epoch <= step) __nanosleep(64);
            __threadfence();
        }
    }
    __syncthreads();
}

// ---------------------------------------------------------------------------
// Kernel 2: persistent LSTM recurrence. 128 blocks x 256 threads.
// Block (bm, bn): bm -> 64 batch rows; bn -> 16 hidden cols across all 4
// gates (strided column mapping). Gates stay in smem, c in registers,
// h double-buffered in global -> 1 grid barrier per step.
// ---------------------------------------------------------------------------
__global__ __launch_bounds__(256) void lstm_persistent(const float* __restrict__ Wh) {
    __shared__ __align__(16) float As[Bk][Bb];
    __shared__ __align__(16) float Bs[Bk][Bn];
    __shared__ __align__(16) float sg[64][68];   // gates tile (padded)

    const int tid = threadIdx.x;
    const int bm = blockIdx.x >> 5;       // 0..3
    const int bn = blockIdx.x & 31;       // 0..31
    const int m0 = bm << 6;               // batch row base
    const int j0 = bn << 4;               // hidden col base (16 wide)

    const int tx = tid & 15;
    const int ty = tid >> 4;
    const int lm  = tid >> 2;             // 0..63
    const int lk4 = (tid & 3) << 2;       // 0,4,8,12

    // B column mapping: c in [0,64) -> gate = c/16, col = j0 + c%16
    const int ncol = ((lm >> 4) << 9) + j0 + (lm & 15);
    const float* WhRow = Wh + (size_t)ncol * HH;   // L1-resident across steps

    // epilogue column base (4 consecutive cols, one gate)
    const int cb = tx << 2;
    const int ncolE = ((cb >> 4) << 9) + j0 + (cb & 15);

    // pointwise mapping
    const int pm = tid >> 2;
    const int pj = (tid << 2) & 15;

    float c_reg[4] = {0.f, 0.f, 0.f, 0.f};

    for (int t = 0; t < TT; ++t) {
        const int p = t & 1;
        const float* hRead = g_hbuf[p];
        unsigned long long accp[4][2] = {};

        const float* aPtr = hRead + (size_t)(m0 + lm) * HH + lk4;

        float4 aN = __ldcg(reinterpret_cast<const float4*>(aPtr));
        float4 bN = *reinterpret_cast<const float4*>(WhRow + lk4);
#pragma unroll 1
        for (int k0 = 0; k0 < HH; k0 += Bk) {
            As[lk4 + 0][lm] = aN.x; As[lk4 + 1][lm] = aN.y;
            As[lk4 + 2][lm] = aN.z; As[lk4 + 3][lm] = aN.w;
            Bs[lk4 + 0][lm] = bN.x; Bs[lk4 + 1][lm] = bN.y;
            Bs[lk4 + 2][lm] = bN.z; Bs[lk4 + 3][lm] = bN.w;
            __syncthreads();
            if (k0 + Bk < HH) {
                aN = __ldcg(reinterpret_cast<const float4*>(aPtr + k0 + Bk));
                bN = *reinterpret_cast<const float4*>(WhRow + k0 + Bk + lk4);
            }
#pragma unroll
            for (int kk = 0; kk < Bk; kk++) {
                float4 a  = *reinterpret_cast<const float4*>(&As[kk][ty << 2]);
                float4 bb = *reinterpret_cast<const float4*>(&Bs[kk][tx << 2]);
                unsigned long long b0p = pk2(bb.x, bb.y);
                unsigned long long b1p = pk2(bb.z, bb.w);
                float ar[4] = {a.x, a.y, a.z, a.w};
#pragma unroll
                for (int i = 0; i < 4; i++) {
                    unsigned long long ai = dup2(ar[i]);
                    fma2(accp[i][0], ai, b0p);
                    fma2(accp[i][1], ai, b1p);
                }
            }
            __syncthreads();
        }

        // add xg[t] and stage gates tile to smem
        const float* xg_t = g_xg + ((size_t)t * BB + m0) * GG;
#pragma unroll
        for (int i = 0; i < 4; i++) {
            int m = (ty << 2) + i;
            float4 xv = __ldcg(reinterpret_cast<const float4*>(xg_t + (size_t)m * GG + ncolE));
            float2 p0 = upk2(accp[i][0]);
            float2 p1 = upk2(accp[i][1]);
            *reinterpret_cast<float4*>(&sg[m][cb]) =
                make_float4(p0.x + xv.x, p0.y + xv.y, p1.x + xv.z, p1.y + xv.w);
        }
        __syncthreads();

        // pointwise cell update: 4 elements per thread, c in registers
        float* hw = g_hbuf[p ^ 1] + (size_t)(m0 + pm) * HH + j0 + pj;
        float hv[4];
#pragma unroll
        for (int e = 0; e < 4; e++) {
            float iv = sg[pm][ 0 + pj + e];
            float fv = sg[pm][16 + pj + e];
            float gv = sg[pm][32 + pj + e];
            float ov = sg[pm][48 + pj + e];
            iv = 1.0f / (1.0f + __expf(-iv));
            fv = 1.0f / (1.0f + __expf(-fv));
            gv = tanhf(gv);
            ov = 1.0f / (1.0f + __expf(-ov));
            float cc = c_reg[e] * fv + iv * gv;
            c_reg[e] = cc;
            hv[e] = ov * tanhf(cc);
        }
        *reinterpret_cast<float4*>(hw) = make_float4(hv[0], hv[1], hv[2], hv[3]);

        __threadfence();   // make h stores visible before barrier publish
        grid_bar(t);
    }
}

// ---------------------------------------------------------------------------
// Kernel 3: init h buffers + barrier state
// ---------------------------------------------------------------------------
__global__ __launch_bounds__(256) void init_kernel() {
    int i = blockIdx.x * blockDim.x + threadIdx.x;
    if (i < BB * HH) { g_hbuf[0][i] = 0.0f; g_hbuf[1][i] = 0.0f; }
    if (i == 0) { g_bar_count = 0; g_epoch = 0; }
}

// ---------------------------------------------------------------------------
// Kernel 4: final FC, warp-per-output: out[b][o] = h[b] . Wfc[o] + bfc[o]
// Final h lives in g_hbuf[TT & 1].
// ---------------------------------------------------------------------------
__global__ __launch_bounds__(256) void fc_kernel(const float* __restrict__ Wfc,
                                                 const float* __restrict__ bfc,
                                                 float* __restrict__ out) {
    int warp = (blockIdx.x * blockDim.x + threadIdx.x) >> 5;
    int lane = threadIdx.x & 31;
    if (warp >= BB * OO) return;
    int b = warp / OO;
    int o = warp - b * OO;
    const float4* hr = reinterpret_cast<const float4*>(g_hbuf[TT & 1] + (size_t)b * HH);
    const float4* wr = reinterpret_cast<const float4*>(Wfc + (size_t)o * HH);
    float s = 0.0f;
#pragma unroll
    for (int k = 0; k < 4; k++) {
        float4 h4 = hr[lane + (k << 5)];
        float4 w4 = wr[lane + (k << 5)];
        s += h4.x * w4.x + h4.y * w4.y + h4.z * w4.z + h4.w * w4.w;
    }
#pragma unroll
    for (int off = 16; off; off >>= 1) s += __shfl_xor_sync(0xffffffffu, s, off);
    if (lane == 0) out[warp] = s + bfc[o];
}

// ---------------------------------------------------------------------------
extern "C" void kernel_launch(void* const* d_in, const int* in_sizes, int n_in,
                              void* d_out, int out_size) {
    const float* x   = (const float*)d_in[0];  // [B,T,I]
    const float* Wx  = (const float*)d_in[1];  // [4H,I]
    const float* bx  = (const float*)d_in[2];  // [4H]
    const float* Wh  = (const float*)d_in[3];  // [4H,H]
    const float* bh  = (const float*)d_in[4];  // [4H]
    const float* Wfc = (const float*)d_in[5];  // [O,H]
    const float* bfc = (const float*)d_in[6];  // [O]
    float* out = (float*)d_out;                // [B,O]

    init_kernel<<<(BB * HH + 255) / 256, 256>>>();

    {
        dim3 grid((TT * BB) / Bb, GG / Bn);
        xg_gemm<<<grid, 256>>>(x, Wx, bx, bh);
    }

    lstm_persistent<<<NBLK, 256>>>(Wh);

    fc_kernel<<<(BB * OO * 32 + 255) / 256, 256>>>(Wfc, bfc, out);
}

// round 4
// speedup vs baseline: 1.0573x; 1.0573x over previous
#include <cuda_runtime.h>
#include <math.h>

#define BB 256
#define TT 500
#define II 256
#define HH 512
#define GG 2048
#define OO 100
#define NBLK 128

typedef unsigned long long ull;

// Scratch (allocation-free)
__device__ float g_xg[(size_t)TT * BB * GG];      // [T][B][4H] x-projections (+bx+bh)
__device__ float g_hbuf[2][BB * HH];              // double-buffered h
__device__ float g_part[2][64 * 64 * 128];        // [kb][pair][m(64)][c(128)] partial gates
__device__ unsigned g_bar_count;
__device__ volatile unsigned g_epoch;

// packed f32x2 helpers
__device__ __forceinline__ void fma2(ull& d, ull a, ull b) {
    asm("fma.rn.f32x2 %0, %1, %2, %0;" : "+l"(d) : "l"(a), "l"(b));
}
__device__ __forceinline__ float2 upk2(ull v) {
    float2 f;
    asm("mov.b64 {%0, %1}, %2;" : "=f"(f.x), "=f"(f.y) : "l"(v));
    return f;
}
__device__ __forceinline__ float red2(ull v) { float2 f = upk2(v); return f.x + f.y; }

// XOR swizzle on float4-granularity row index (kills 128B-periodic bank clash)
__device__ __forceinline__ int swz(int r) { return r ^ ((r >> 3) & 7); }

// ---------------------------------------------------------------------------
// Kernel 1: xg = x @ Wx^T + bx + bh.  Tile 128x128, Bk=16, 256 thr, 8x8 utile.
// Grid: (T*B/128, 2048/128) = (1000, 16)
// ---------------------------------------------------------------------------
__global__ __launch_bounds__(256, 1) void xg_gemm(const float* __restrict__ x,
                                                  const float* __restrict__ Wx,
                                                  const float* __restrict__ bx,
                                                  const float* __restrict__ bh) {
    __shared__ __align__(16) float4 As4[4 * 128];   // [quad][row] swizzled
    __shared__ __align__(16) float4 Bs4[4 * 128];

    const int mBase = blockIdx.x * 128;
    const int nBase = blockIdx.y * 128;
    const int t  = mBase >> 8;
    const int b0 = mBase & 255;

    const int tid = threadIdx.x;
    const int tx = tid & 15;          // n = tx*8 + j
    const int ty = tid >> 4;          // m = ty*8 + i

    // staging: float4 f in {tid, tid+256}: row = f>>2, quad = f&3
    const int ra = tid >> 2;          // 0..63 (and +64)
    const int qa = tid & 3;

    const float* aG0 = x + ((size_t)(b0 + ra) * TT + t) * II + qa * 4;
    const float* aG1 = x + ((size_t)(b0 + ra + 64) * TT + t) * II + qa * 4;
    const float* bG0 = Wx + (size_t)(nBase + ra) * II + qa * 4;
    const float* bG1 = Wx + (size_t)(nBase + ra + 64) * II + qa * 4;

    const int sA0 = qa * 128 + swz(ra);
    const int sA1 = qa * 128 + swz(ra + 64);

    float bias[8];
#pragma unroll
    for (int j = 0; j < 8; j++) {
        int n = nBase + tx * 8 + j;
        bias[j] = bx[n] + bh[n];
    }

    const int aBase = ty * 8;
    const int aX = ty & 7;
    const int bBase = tx * 8;
    const int bX = tx & 7;

    ull acc[8][8] = {};

    float4 a0 = *(const float4*)aG0;
    float4 a1 = *(const float4*)aG1;
    float4 c0 = *(const float4*)bG0;
    float4 c1 = *(const float4*)bG1;

    for (int kt = 0; kt < 16; kt++) {
        As4[sA0] = a0; As4[sA1] = a1;
        Bs4[sA0] = c0; Bs4[sA1] = c1;
        __syncthreads();
        if (kt < 15) {
            int off = (kt + 1) * 16;
            a0 = *(const float4*)(aG0 + off);
            a1 = *(const float4*)(aG1 + off);
            c0 = *(const float4*)(bG0 + off);
            c1 = *(const float4*)(bG1 + off);
        }
#pragma unroll
        for (int q = 0; q < 4; q++) {
            ulonglong2 av[8];
#pragma unroll
            for (int i = 0; i < 8; i++)
                av[i] = *reinterpret_cast<const ulonglong2*>(&As4[q * 128 + aBase + (i ^ aX)]);
#pragma unroll
            for (int j = 0; j < 8; j++) {
                ulonglong2 bv = *reinterpret_cast<const ulonglong2*>(&Bs4[q * 128 + bBase + (j ^ bX)]);
#pragma unroll
                for (int i = 0; i < 8; i++) {
                    fma2(acc[i][j], av[i].x, bv.x);
                    fma2(acc[i][j], av[i].y, bv.y);
                }
            }
        }
        __syncthreads();
    }

#pragma unroll
    for (int i = 0; i < 8; i++) {
        float* orow = g_xg + (size_t)(mBase + ty * 8 + i) * GG + nBase + tx * 8;
#pragma unroll
        for (int jq = 0; jq < 2; jq++) {
            float4 o;
            o.x = red2(acc[i][jq * 4 + 0]) + bias[jq * 4 + 0];
            o.y = red2(acc[i][jq * 4 + 1]) + bias[jq * 4 + 1];
            o.z = red2(acc[i][jq * 4 + 2]) + bias[jq * 4 + 2];
            o.w = red2(acc[i][jq * 4 + 3]) + bias[jq * 4 + 3];
            *reinterpret_cast<float4*>(orow + jq * 4) = o;
        }
    }
}

// ---------------------------------------------------------------------------
// Grid-wide software barrier
// ---------------------------------------------------------------------------
__device__ __forceinline__ void grid_bar(unsigned ep) {
    __syncthreads();
    if (threadIdx.x == 0) {
        unsigned arrived = atomicAdd(&g_bar_count, 1);
        if (arrived == NBLK - 1) {
            g_bar_count = 0;
            __threadfence();
            g_epoch = ep + 1;
        } else {
            while (g_epoch <= ep) __nanosleep(64);
            __threadfence();
        }
    }
    __syncthreads();
}

// ---------------------------------------------------------------------------
// Kernel 2: persistent LSTM recurrence. 128 blocks x 128 threads.
// Output tile per block-PAIR: 64 batch rows x 128 gate-cols (= 32 hidden cols
// across the 4 gates, strided). Split-K: kb=0 -> k[0,256), kb=1 -> k[256,512).
// Partials through L2 (g_part), 2 grid barriers per step. c in registers.
// ---------------------------------------------------------------------------
__global__ __launch_bounds__(128, 1) void lstm_persistent(const float* __restrict__ Wh) {
    __shared__ __align__(16) float4 As4[4 * 64];
    __shared__ __align__(16) float4 Bs4[4 * 128];

    const int tid = threadIdx.x;
    const int kb   = blockIdx.x & 1;
    const int pair = blockIdx.x >> 1;     // 0..63
    const int pm = pair >> 4;             // 0..3  -> batch rows
    const int pn = pair & 15;             // 0..15 -> hidden col group
    const int m0 = pm << 6;

    const int tx = tid & 15;              // n = tx*8 + j (local gate col)
    const int ty = tid >> 4;              // 0..7, m = ty*8 + i

    // A staging: float4 f in {tid, tid+128}: row = f>>2 (0..63), quad = f&3
    const int ra = tid >> 2;              // 0..31 (and +32)
    const int qa = tid & 3;
    const int sA0 = qa * 64 + swz(ra);
    const int sA1 = qa * 64 + swz(ra + 32);

    // B staging: 4 rows per thread: rB[s] = ra + 32*s, local col -> global Wh row
    const float* wp[4];
    int sB[4];
#pragma unroll
    for (int s = 0; s < 4; s++) {
        int r = ra + 32 * s;                           // local n, 0..127
        int gcol = ((r >> 5) << 9) + (pn << 5) + (r & 31);
        wp[s] = Wh + (size_t)gcol * HH + kb * 256 + qa * 4;
        sB[s] = qa * 128 + swz(r);
    }

    const int aBase = ty * 8;
    const int aX = ty & 7;
    const int bBase = tx * 8;
    const int bX = tx & 7;

    // pointwise mapping: 8 cells per thread
    const int pwm = kb * 32 + (tid >> 2);   // batch row within tile (0..63)
    const int pwj = (tid & 3) * 8;          // hidden col offset (0,8,16,24)

    float* myPart = g_part[kb] + (size_t)pair * 64 * 128;
    const float* pt0 = g_part[0] + (size_t)pair * 64 * 128 + pwm * 128;
    const float* pt1 = g_part[1] + (size_t)pair * 64 * 128 + pwm * 128;

    float c_reg[8] = {0.f, 0.f, 0.f, 0.f, 0.f, 0.f, 0.f, 0.f};

    for (int t = 0; t < TT; ++t) {
        const int cur = t & 1;
        const float* hbase = g_hbuf[cur] + (size_t)m0 * HH + kb * 256;

        ull acc[8][8] = {};

        float4 a0 = __ldcg((const float4*)(hbase + (size_t)ra * HH + qa * 4));
        float4 a1 = __ldcg((const float4*)(hbase + (size_t)(ra + 32) * HH + qa * 4));
        float4 w0 = *(const float4*)(wp[0]);
        float4 w1 = *(const float4*)(wp[1]);
        float4 w2 = *(const float4*)(wp[2]);
        float4 w3 = *(const float4*)(wp[3]);

        for (int kt = 0; kt < 16; kt++) {
            As4[sA0] = a0; As4[sA1] = a1;
            Bs4[sB[0]] = w0; Bs4[sB[1]] = w1; Bs4[sB[2]] = w2; Bs4[sB[3]] = w3;
            __syncthreads();
            if (kt < 15) {
                int off = (kt + 1) * 16;
                a0 = __ldcg((const float4*)(hbase + (size_t)ra * HH + off + qa * 4));
                a1 = __ldcg((const float4*)(hbase + (size_t)(ra + 32) * HH + off + qa * 4));
                w0 = *(const float4*)(wp[0] + off);
                w1 = *(const float4*)(wp[1] + off);
                w2 = *(const float4*)(wp[2] + off);
                w3 = *(const float4*)(wp[3] + off);
            }
#pragma unroll
            for (int q = 0; q < 4; q++) {
                ulonglong2 av[8];
#pragma unroll
                for (int i = 0; i < 8; i++)
                    av[i] = *reinterpret_cast<const ulonglong2*>(&As4[q * 64 + aBase + (i ^ aX)]);
#pragma unroll
                for (int j = 0; j < 8; j++) {
                    ulonglong2 bv = *reinterpret_cast<const ulonglong2*>(&Bs4[q * 128 + bBase + (j ^ bX)]);
#pragma unroll
                    for (int i = 0; i < 8; i++) {
                        fma2(acc[i][j], av[i].x, bv.x);
                        fma2(acc[i][j], av[i].y, bv.y);
                    }
                }
            }
            __syncthreads();
        }

        // write partials (local layout [m][c])
#pragma unroll
        for (int i = 0; i < 8; i++) {
            float* prow = myPart + (size_t)(ty * 8 + i) * 128 + tx * 8;
#pragma unroll
            for (int jq = 0; jq < 2; jq++) {
                float4 o;
                o.x = red2(acc[i][jq * 4 + 0]);
                o.y = red2(acc[i][jq * 4 + 1]);
                o.z = red2(acc[i][jq * 4 + 2]);
                o.w = red2(acc[i][jq * 4 + 3]);
                *reinterpret_cast<float4*>(prow + jq * 4) = o;
            }
        }
        __threadfence();
        grid_bar(2 * t);

        // pointwise: 8 cells (row pwm, hidden cols pwj..pwj+7)
        const float* xgr = g_xg + ((size_t)t * BB + m0 + pwm) * GG + (pn << 5) + pwj;
        float gates[4][8];
#pragma unroll
        for (int g = 0; g < 4; g++) {
            float4 u0 = __ldcg((const float4*)(pt0 + g * 32 + pwj));
            float4 u1 = __ldcg((const float4*)(pt0 + g * 32 + pwj + 4));
            float4 v0 = __ldcg((const float4*)(pt1 + g * 32 + pwj));
            float4 v1 = __ldcg((const float4*)(pt1 + g * 32 + pwj + 4));
            float4 z0 = __ldcg((const float4*)(xgr + (size_t)g * HH));
            float4 z1 = __ldcg((const float4*)(xgr + (size_t)g * HH + 4));
            gates[g][0] = u0.x + v0.x + z0.x;
            gates[g][1] = u0.y + v0.y + z0.y;
            gates[g][2] = u0.z + v0.z + z0.z;
            gates[g][3] = u0.w + v0.w + z0.w;
            gates[g][4] = u1.x + v1.x + z1.x;
            gates[g][5] = u1.y + v1.y + z1.y;
            gates[g][6] = u1.z + v1.z + z1.z;
            gates[g][7] = u1.w + v1.w + z1.w;
        }
        float hv[8];
#pragma unroll
        for (int e = 0; e < 8; e++) {
            float iv = 1.0f / (1.0f + __expf(-gates[0][e]));
            float fv = 1.0f / (1.0f + __expf(-gates[1][e]));
            float gv = tanhf(gates[2][e]);
            float ov = 1.0f / (1.0f + __expf(-gates[3][e]));
            float cc = c_reg[e] * fv + iv * gv;
            c_reg[e] = cc;
            hv[e] = ov * tanhf(cc);
        }
        float* hw = g_hbuf[cur ^ 1] + (size_t)(m0 + pwm) * HH + (pn << 5) + pwj;
        *reinterpret_cast<float4*>(hw)     = make_float4(hv[0], hv[1], hv[2], hv[3]);
        *reinterpret_cast<float4*>(hw + 4) = make_float4(hv[4], hv[5], hv[6], hv[7]);

        __threadfence();
        grid_bar(2 * t + 1);
    }
}

// ---------------------------------------------------------------------------
__global__ __launch_bounds__(256) void init_kernel() {
    int i = blockIdx.x * blockDim.x + threadIdx.x;
    if (i < BB * HH) { g_hbuf[0][i] = 0.0f; g_hbuf[1][i] = 0.0f; }
    if (i == 0) { g_bar_count = 0; g_epoch = 0; }
}

// ---------------------------------------------------------------------------
__global__ __launch_bounds__(256) void fc_kernel(const float* __restrict__ Wfc,
                                                 const float* __restrict__ bfc,
                                                 float* __restrict__ out) {
    int warp = (blockIdx.x * blockDim.x + threadIdx.x) >> 5;
    int lane = threadIdx.x & 31;
    if (warp >= BB * OO) return;
    int b = warp / OO;
    int o = warp - b * OO;
    const float4* hr = reinterpret_cast<const float4*>(g_hbuf[TT & 1] + (size_t)b * HH);
    const float4* wr = reinterpret_cast<const float4*>(Wfc + (size_t)o * HH);
    float s = 0.0f;
#pragma unroll
    for (int k = 0; k < 4; k++) {
        float4 h4 = hr[lane + (k << 5)];
        float4 w4 = wr[lane + (k << 5)];
        s += h4.x * w4.x + h4.y * w4.y + h4.z * w4.z + h4.w * w4.w;
    }
#pragma unroll
    for (int off = 16; off; off >>= 1) s += __shfl_xor_sync(0xffffffffu, s, off);
    if (lane == 0) out[warp] = s + bfc[o];
}

// ---------------------------------------------------------------------------
extern "C" void kernel_launch(void* const* d_in, const int* in_sizes, int n_in,
                              void* d_out, int out_size) {
    const float* x   = (const float*)d_in[0];
    const float* Wx  = (const float*)d_in[1];
    const float* bx  = (const float*)d_in[2];
    const float* Wh  = (const float*)d_in[3];
    const float* bh  = (const float*)d_in[4];
    const float* Wfc = (const float*)d_in[5];
    const float* bfc = (const float*)d_in[6];
    float* out = (float*)d_out;

    init_kernel<<<(BB * HH + 255) / 256, 256>>>();

    {
        dim3 grid((TT * BB) / 128, GG / 128);   // (1000, 16)
        xg_gemm<<<grid, 256>>>(x, Wx, bx, bh);
    }

    lstm_persistent<<<NBLK, 128>>>(Wh);

    fc_kernel<<<(BB * OO * 32 + 255) / 256, 256>>>(Wfc, bfc, out);
}

// round 5
// speedup vs baseline: 1.3158x; 1.2444x over previous
#include <cuda_runtime.h>
#include <math.h>

#define BB 256
#define TT 500
#define II 256
#define HH 512
#define GG 2048
#define OO 100
#define NBLK 128

typedef unsigned long long ull;

// Scratch (allocation-free)
__device__ float g_xg[(size_t)TT * BB * GG];      // [T][B][4H] x-projections (+bx+bh)
__device__ float g_hbuf[2][BB * HH];              // double-buffered h
__device__ unsigned g_bar_count;
__device__ volatile unsigned g_epoch;

// packed f32x2 helpers
__device__ __forceinline__ void fma2(ull& d, ull a, ull b) {
    asm("fma.rn.f32x2 %0, %1, %2, %0;" : "+l"(d) : "l"(a), "l"(b));
}
__device__ __forceinline__ float red2(ull v) {
    float2 f;
    asm("mov.b64 {%0, %1}, %2;" : "=f"(f.x), "=f"(f.y) : "l"(v));
    return f.x + f.y;
}
__device__ __forceinline__ int swz(int r) { return r ^ ((r >> 3) & 7); }

__device__ __forceinline__ float sigm(float x) { return 1.0f / (1.0f + __expf(-x)); }
__device__ __forceinline__ float tanh_fast(float x) { return 1.0f - 2.0f / (1.0f + __expf(2.0f * x)); }

// ---------------------------------------------------------------------------
// Kernel 1: xg = x @ Wx^T + bx + bh.  Tile 128x128, Bk=16, 256 thr, 8x8 utile.
// (round-4 version, measured near its fma floor)
// ---------------------------------------------------------------------------
__global__ __launch_bounds__(256, 1) void xg_gemm(const float* __restrict__ x,
                                                  const float* __restrict__ Wx,
                                                  const float* __restrict__ bx,
                                                  const float* __restrict__ bh) {
    __shared__ __align__(16) float4 As4[4 * 128];
    __shared__ __align__(16) float4 Bs4[4 * 128];

    const int mBase = blockIdx.x * 128;
    const int nBase = blockIdx.y * 128;
    const int t  = mBase >> 8;
    const int b0 = mBase & 255;

    const int tid = threadIdx.x;
    const int tx = tid & 15;
    const int ty = tid >> 4;

    const int ra = tid >> 2;
    const int qa = tid & 3;

    const float* aG0 = x + ((size_t)(b0 + ra) * TT + t) * II + qa * 4;
    const float* aG1 = x + ((size_t)(b0 + ra + 64) * TT + t) * II + qa * 4;
    const float* bG0 = Wx + (size_t)(nBase + ra) * II + qa * 4;
    const float* bG1 = Wx + (size_t)(nBase + ra + 64) * II + qa * 4;

    const int sA0 = qa * 128 + swz(ra);
    const int sA1 = qa * 128 + swz(ra + 64);

    float bias[8];
#pragma unroll
    for (int j = 0; j < 8; j++) {
        int n = nBase + tx * 8 + j;
        bias[j] = bx[n] + bh[n];
    }

    const int aBase = ty * 8;
    const int aX = ty & 7;
    const int bBase = tx * 8;
    const int bX = tx & 7;

    ull acc[8][8] = {};

    float4 a0 = *(const float4*)aG0;
    float4 a1 = *(const float4*)aG1;
    float4 c0 = *(const float4*)bG0;
    float4 c1 = *(const float4*)bG1;

    for (int kt = 0; kt < 16; kt++) {
        As4[sA0] = a0; As4[sA1] = a1;
        Bs4[sA0] = c0; Bs4[sA1] = c1;
        __syncthreads();
        if (kt < 15) {
            int off = (kt + 1) * 16;
            a0 = *(const float4*)(aG0 + off);
            a1 = *(const float4*)(aG1 + off);
            c0 = *(const float4*)(bG0 + off);
            c1 = *(const float4*)(bG1 + off);
        }
#pragma unroll
        for (int q = 0; q < 4; q++) {
            ulonglong2 av[8];
#pragma unroll
            for (int i = 0; i < 8; i++)
                av[i] = *reinterpret_cast<const ulonglong2*>(&As4[q * 128 + aBase + (i ^ aX)]);
#pragma unroll
            for (int j = 0; j < 8; j++) {
                ulonglong2 bv = *reinterpret_cast<const ulonglong2*>(&Bs4[q * 128 + bBase + (j ^ bX)]);
#pragma unroll
                for (int i = 0; i < 8; i++) {
                    fma2(acc[i][j], av[i].x, bv.x);
                    fma2(acc[i][j], av[i].y, bv.y);
                }
            }
        }
        __syncthreads();
    }

#pragma unroll
    for (int i = 0; i < 8; i++) {
        float* orow = g_xg + (size_t)(mBase + ty * 8 + i) * GG + nBase + tx * 8;
#pragma unroll
        for (int jq = 0; jq < 2; jq++) {
            float4 o;
            o.x = red2(acc[i][jq * 4 + 0]) + bias[jq * 4 + 0];
            o.y = red2(acc[i][jq * 4 + 1]) + bias[jq * 4 + 1];
            o.z = red2(acc[i][jq * 4 + 2]) + bias[jq * 4 + 2];
            o.w = red2(acc[i][jq * 4 + 3]) + bias[jq * 4 + 3];
            *reinterpret_cast<float4*>(orow + jq * 4) = o;
        }
    }
}

// ---------------------------------------------------------------------------
// Grid-wide software barrier (callers fence their global stores first)
// ---------------------------------------------------------------------------
__device__ __forceinline__ void grid_bar(unsigned ep) {
    __syncthreads();
    if (threadIdx.x == 0) {
        unsigned arrived = atomicAdd(&g_bar_count, 1);
        if (arrived == NBLK - 1) {
            g_bar_count = 0;
            __threadfence();
            g_epoch = ep + 1;
        } else {
            while (g_epoch <= ep) __nanosleep(32);
            __threadfence();
        }
    }
    __syncthreads();
}

// ---------------------------------------------------------------------------
// Kernel 2: persistent LSTM recurrence. 128 blocks x 256 threads.
// Block (bm, bn): 64 batch rows x (16 hidden cols x 4 gates, strided).
// Thread (tx, ty): rows {ty+16i}, hidden col j0+tx, all four gates in acc[i][0..3]
// -> pointwise entirely in registers. K=512, Bk=32, 2-stage smem double buffer.
// One grid barrier per step.
// ---------------------------------------------------------------------------
__global__ __launch_bounds__(256, 1) void lstm_persistent(const float* __restrict__ Wh) {
    __shared__ __align__(16) float4 As[2][64 * 8];
    __shared__ __align__(16) float4 Bs[2][64 * 8];

    const int tid = threadIdx.x;
    const int bm = blockIdx.x >> 5;       // 0..3
    const int bn = blockIdx.x & 31;       // 0..31
    const int m0 = bm << 6;
    const int j0 = bn << 4;

    const int tx = tid & 15;
    const int ty = tid >> 4;

    // staging: thread loads chunk (row r, ch) for r0 and r0+32
    const int r0 = tid >> 3;              // 0..31
    const int ch = tid & 7;               // float4 chunk within 32-k row
    const int r1 = r0 + 32;

    // B local row r -> global Wh row: gate = r>>4, hidden = j0 + (r&15)
    const int gc0 = ((r0 >> 4) << 9) + j0 + (r0 & 15);
    const int gc1 = ((r1 >> 4) << 9) + j0 + (r1 & 15);
    const float* WhP0 = Wh + (size_t)gc0 * HH + ch * 4;
    const float* WhP1 = Wh + (size_t)gc1 * HH + ch * 4;

    const int s0 = r0 * 8 + (ch ^ (r0 & 7));
    const int s1 = r1 * 8 + (ch ^ (r1 & 7));

    // compute-side smem indices (row R, chunk kk -> R*8 + (kk ^ (R&7)))
    int aIdx[4], bIdx[4];
#pragma unroll
    for (int i = 0; i < 4; i++) { int R = ty + 16 * i; aIdx[i] = R * 8; }
#pragma unroll
    for (int j = 0; j < 4; j++) { int R = tx + 16 * j; bIdx[j] = R * 8; }
    const int aX = ty & 7;   // (ty+16i)&7 == ty&7
    const int bX = tx & 7;

    float c_reg[4] = {0.f, 0.f, 0.f, 0.f};

    for (int t = 0; t < TT; ++t) {
        const int cur = t & 1;
        const float* hB = g_hbuf[cur];
        const float* aP0 = hB + (size_t)(m0 + r0) * HH + ch * 4;
        const float* aP1 = hB + (size_t)(m0 + r1) * HH + ch * 4;

        ull acc[4][4] = {};
        float xq[4][4];

        float4 ra0 = __ldcg((const float4*)aP0);
        float4 ra1 = __ldcg((const float4*)aP1);
        float4 rb0 = *(const float4*)WhP0;
        float4 rb1 = *(const float4*)WhP1;
        As[0][s0] = ra0; As[0][s1] = ra1;
        Bs[0][s0] = rb0; Bs[0][s1] = rb1;
        __syncthreads();

        for (int kt = 0; kt < 16; kt++) {
            const int st = kt & 1;
            if (kt < 15) {
                int off = (kt + 1) * 32;
                ra0 = __ldcg((const float4*)(aP0 + off));
                ra1 = __ldcg((const float4*)(aP1 + off));
                rb0 = *(const float4*)(WhP0 + off);
                rb1 = *(const float4*)(WhP1 + off);
            } else {
                // prefetch xg[t] tile (DRAM) under the last compute stage
#pragma unroll
                for (int i = 0; i < 4; i++)
#pragma unroll
                    for (int j = 0; j < 4; j++)
                        xq[i][j] = __ldcg(g_xg + ((size_t)t * BB + m0 + ty + 16 * i) * GG
                                          + j * HH + j0 + tx);
            }
#pragma unroll
            for (int kk = 0; kk < 8; kk++) {
                ulonglong2 av[4], bv[4];
#pragma unroll
                for (int i = 0; i < 4; i++)
                    av[i] = *reinterpret_cast<const ulonglong2*>(&As[st][aIdx[i] + (kk ^ aX)]);
#pragma unroll
                for (int j = 0; j < 4; j++)
                    bv[j] = *reinterpret_cast<const ulonglong2*>(&Bs[st][bIdx[j] + (kk ^ bX)]);
#pragma unroll
                for (int i = 0; i < 4; i++)
#pragma unroll
                    for (int j = 0; j < 4; j++) {
                        fma2(acc[i][j], av[i].x, bv[j].x);
                        fma2(acc[i][j], av[i].y, bv[j].y);
                    }
            }
            if (kt < 15) {
                const int ns = (kt + 1) & 1;
                As[ns][s0] = ra0; As[ns][s1] = ra1;
                Bs[ns][s0] = rb0; Bs[ns][s1] = rb1;
                __syncthreads();
            }
        }

        // pointwise in registers: cell (m0+ty+16i, hidden j0+tx)
        float* hOut = g_hbuf[cur ^ 1];
#pragma unroll
        for (int i = 0; i < 4; i++) {
            float gi = red2(acc[i][0]) + xq[i][0];
            float gf = red2(acc[i][1]) + xq[i][1];
            float gg = red2(acc[i][2]) + xq[i][2];
            float go = red2(acc[i][3]) + xq[i][3];
            float iv = sigm(gi);
            float fv = sigm(gf);
            float gv = tanh_fast(gg);
            float ov = sigm(go);
            float cc = c_reg[i] * fv + iv * gv;
            c_reg[i] = cc;
            hOut[(size_t)(m0 + ty + 16 * i) * HH + j0 + tx] = ov * tanh_fast(cc);
        }

        __threadfence();
        grid_bar(t);
    }
}

// ---------------------------------------------------------------------------
__global__ __launch_bounds__(256) void init_kernel() {
    int i = blockIdx.x * blockDim.x + threadIdx.x;
    if (i < BB * HH) { g_hbuf[0][i] = 0.0f; g_hbuf[1][i] = 0.0f; }
    if (i == 0) { g_bar_count = 0; g_epoch = 0; }
}

// ---------------------------------------------------------------------------
__global__ __launch_bounds__(256) void fc_kernel(const float* __restrict__ Wfc,
                                                 const float* __restrict__ bfc,
                                                 float* __restrict__ out) {
    int warp = (blockIdx.x * blockDim.x + threadIdx.x) >> 5;
    int lane = threadIdx.x & 31;
    if (warp >= BB * OO) return;
    int b = warp / OO;
    int o = warp - b * OO;
    const float4* hr = reinterpret_cast<const float4*>(g_hbuf[TT & 1] + (size_t)b * HH);
    const float4* wr = reinterpret_cast<const float4*>(Wfc + (size_t)o * HH);
    float s = 0.0f;
#pragma unroll
    for (int k = 0; k < 4; k++) {
        float4 h4 = hr[lane + (k << 5)];
        float4 w4 = wr[lane + (k << 5)];
        s += h4.x * w4.x + h4.y * w4.y + h4.z * w4.z + h4.w * w4.w;
    }
#pragma unroll
    for (int off = 16; off; off >>= 1) s += __shfl_xor_sync(0xffffffffu, s, off);
    if (lane == 0) out[warp] = s + bfc[o];
}

// ---------------------------------------------------------------------------
extern "C" void kernel_launch(void* const* d_in, const int* in_sizes, int n_in,
                              void* d_out, int out_size) {
    const float* x   = (const float*)d_in[0];
    const float* Wx  = (const float*)d_in[1];
    const float* bx  = (const float*)d_in[2];
    const float* Wh  = (const float*)d_in[3];
    const float* bh  = (const float*)d_in[4];
    const float* Wfc = (const float*)d_in[5];
    const float* bfc = (const float*)d_in[6];
    float* out = (float*)d_out;

    init_kernel<<<(BB * HH + 255) / 256, 256>>>();

    {
        dim3 grid((TT * BB) / 128, GG / 128);   // (1000, 16)
        xg_gemm<<<grid, 256>>>(x, Wx, bx, bh);
    }

    lstm_persistent<<<NBLK, 256>>>(Wh);

    fc_kernel<<<(BB * OO * 32 + 255) / 256, 256>>>(Wfc, bfc, out);
}

// round 8
// speedup vs baseline: 2.0138x; 1.5305x over previous
#include <cuda_runtime.h>
#include <cuda_bf16.h>
#include <math.h>
#include <cstdint>

#define BB 256
#define TT 500
#define II 256
#define HH 512
#define GG 2048
#define OO 100
#define NBLK 128

typedef unsigned long long ull;

// ------------------------- global scratch (no allocs) -----------------------
__device__ float g_xg[(size_t)TT * BB * GG];            // [T][B][4H]
__device__ __nv_bfloat16 g_hsplit[2][BB * 1024];        // [buf][b][k]: k<512 h1, >=512 h2
__device__ float g_hfp[BB * HH];                        // fp32 h (for fc)
__device__ __nv_bfloat16 g_W1[GG * HH];                 // bf16(Wh)
__device__ __nv_bfloat16 g_W2[GG * HH];                 // bf16(Wh - W1)
__device__ unsigned g_bar_count;
__device__ volatile unsigned g_epoch;

// ------------------------- helpers ------------------------------------------
__device__ __forceinline__ void fma2(ull& d, ull a, ull b) {
    asm("fma.rn.f32x2 %0, %1, %2, %0;" : "+l"(d) : "l"(a), "l"(b));
}
__device__ __forceinline__ float red2(ull v) {
    float2 f;
    asm("mov.b64 {%0, %1}, %2;" : "=f"(f.x), "=f"(f.y) : "l"(v));
    return f.x + f.y;
}
__device__ __forceinline__ int swz(int r) { return r ^ ((r >> 3) & 7); }
__device__ __forceinline__ float sigm(float x) { return 1.0f / (1.0f + __expf(-x)); }
__device__ __forceinline__ float tanh_fast(float x) { return 1.0f - 2.0f / (1.0f + __expf(2.0f * x)); }
__device__ __forceinline__ uint32_t smem_u32(const void* p) {
    return (uint32_t)__cvta_generic_to_shared(p);
}
__device__ __forceinline__ void ldsm4(uint32_t& a0, uint32_t& a1, uint32_t& a2, uint32_t& a3,
                                      uint32_t addr) {
    asm volatile("ldmatrix.sync.aligned.m8n8.x4.shared.b16 {%0,%1,%2,%3}, [%4];"
                 : "=r"(a0), "=r"(a1), "=r"(a2), "=r"(a3) : "r"(addr));
}
__device__ __forceinline__ void mma_bf16(float* d, uint32_t a0, uint32_t a1, uint32_t a2,
                                         uint32_t a3, uint32_t b0, uint32_t b1) {
    asm volatile(
        "mma.sync.aligned.m16n8k16.row.col.f32.bf16.bf16.f32 "
        "{%0,%1,%2,%3}, {%4,%5,%6,%7}, {%8,%9}, {%0,%1,%2,%3};"
        : "+f"(d[0]), "+f"(d[1]), "+f"(d[2]), "+f"(d[3])
        : "r"(a0), "r"(a1), "r"(a2), "r"(a3), "r"(b0), "r"(b1));
}

// ---------------------------------------------------------------------------
// Kernel 1: xg = x @ Wx^T + bx + bh (FFMA2 SIMT, near its floor)
// ---------------------------------------------------------------------------
__global__ __launch_bounds__(256, 1) void xg_gemm(const float* __restrict__ x,
                                                  const float* __restrict__ Wx,
                                                  const float* __restrict__ bx,
                                                  const float* __restrict__ bh) {
    __shared__ __align__(16) float4 As4[4 * 128];
    __shared__ __align__(16) float4 Bs4[4 * 128];

    const int mBase = blockIdx.x * 128;
    const int nBase = blockIdx.y * 128;
    const int t  = mBase >> 8;
    const int b0 = mBase & 255;

    const int tid = threadIdx.x;
    const int tx = tid & 15;
    const int ty = tid >> 4;
    const int ra = tid >> 2;
    const int qa = tid & 3;

    const float* aG0 = x + ((size_t)(b0 + ra) * TT + t) * II + qa * 4;
    const float* aG1 = x + ((size_t)(b0 + ra + 64) * TT + t) * II + qa * 4;
    const float* bG0 = Wx + (size_t)(nBase + ra) * II + qa * 4;
    const float* bG1 = Wx + (size_t)(nBase + ra + 64) * II + qa * 4;

    const int sA0 = qa * 128 + swz(ra);
    const int sA1 = qa * 128 + swz(ra + 64);

    float bias[8];
#pragma unroll
    for (int j = 0; j < 8; j++) {
        int n = nBase + tx * 8 + j;
        bias[j] = bx[n] + bh[n];
    }

    const int aBase = ty * 8;
    const int aX = ty & 7;
    const int bBase = tx * 8;
    const int bX = tx & 7;

    ull acc[8][8] = {};

    float4 a0 = *(const float4*)aG0;
    float4 a1 = *(const float4*)aG1;
    float4 c0 = *(const float4*)bG0;
    float4 c1 = *(const float4*)bG1;

    for (int kt = 0; kt < 16; kt++) {
        As4[sA0] = a0; As4[sA1] = a1;
        Bs4[sA0] = c0; Bs4[sA1] = c1;
        __syncthreads();
        if (kt < 15) {
            int off = (kt + 1) * 16;
            a0 = *(const float4*)(aG0 + off);
            a1 = *(const float4*)(aG1 + off);
            c0 = *(const float4*)(bG0 + off);
            c1 = *(const float4*)(bG1 + off);
        }
#pragma unroll
        for (int q = 0; q < 4; q++) {
            ulonglong2 av[8];
#pragma unroll
            for (int i = 0; i < 8; i++)
                av[i] = *reinterpret_cast<const ulonglong2*>(&As4[q * 128 + aBase + (i ^ aX)]);
#pragma unroll
            for (int j = 0; j < 8; j++) {
                ulonglong2 bv = *reinterpret_cast<const ulonglong2*>(&Bs4[q * 128 + bBase + (j ^ bX)]);
#pragma unroll
                for (int i = 0; i < 8; i++) {
                    fma2(acc[i][j], av[i].x, bv.x);
                    fma2(acc[i][j], av[i].y, bv.y);
                }
            }
        }
        __syncthreads();
    }

#pragma unroll
    for (int i = 0; i < 8; i++) {
        float* orow = g_xg + (size_t)(mBase + ty * 8 + i) * GG + nBase + tx * 8;
#pragma unroll
        for (int jq = 0; jq < 2; jq++) {
            float4 o;
            o.x = red2(acc[i][jq * 4 + 0]) + bias[jq * 4 + 0];
            o.y = red2(acc[i][jq * 4 + 1]) + bias[jq * 4 + 1];
            o.z = red2(acc[i][jq * 4 + 2]) + bias[jq * 4 + 2];
            o.w = red2(acc[i][jq * 4 + 3]) + bias[jq * 4 + 3];
            *reinterpret_cast<float4*>(orow + jq * 4) = o;
        }
    }
}

// ---------------------------------------------------------------------------
// Prep: split Wh into bf16 W1/W2; zero h-split buffers; reset barrier
// ---------------------------------------------------------------------------
__global__ __launch_bounds__(256) void prep_kernel(const float* __restrict__ Wh) {
    int stride = gridDim.x * blockDim.x;
    for (int idx = blockIdx.x * blockDim.x + threadIdx.x; idx < GG * HH; idx += stride) {
        float w = Wh[idx];
        __nv_bfloat16 w1 = __float2bfloat16(w);
        g_W1[idx] = w1;
        g_W2[idx] = __float2bfloat16(w - __bfloat162float(w1));
    }
    __nv_bfloat16 z = __float2bfloat16(0.0f);
    for (int idx = blockIdx.x * blockDim.x + threadIdx.x; idx < BB * 1024; idx += stride) {
        g_hsplit[0][idx] = z;
        g_hsplit[1][idx] = z;
    }
    if (blockIdx.x == 0 && threadIdx.x == 0) { g_bar_count = 0; g_epoch = 0; }
}

// ---------------------------------------------------------------------------
__device__ __forceinline__ void grid_bar(unsigned ep) {
    __syncthreads();
    if (threadIdx.x == 0) {
        unsigned arrived = atomicAdd(&g_bar_count, 1);
        if (arrived == NBLK - 1) {
            g_bar_count = 0;
            __threadfence();
            g_epoch = ep + 1;
        } else {
            while (g_epoch <= ep) __nanosleep(32);
            __threadfence();
        }
    }
    __syncthreads();
}

// ---------------------------------------------------------------------------
// Kernel 2: persistent HMMA LSTM recurrence. 128 blocks x 256 threads.
// Block: 64 batch rows x 64 gate-cols (= 16 hidden cols x 4 gates interleaved:
// local n -> gate=(n>>3)&3, hid=j0+(n>>5)*8+(n&7)). Weights W1|W2 (K=1024)
// resident in smem (bf16, ldmatrix-friendly padded layout, stride==1 mod 8
// 16B-banks -> conflict-free). Per step, 12 chunk passes realize
// h1W1 + h1W2 + h2W1 exactly on tensor cores. Pointwise fully in registers.
// B fragments via NON-trans ldmatrix from [n][k] rows (k-adjacent packing).
// SMEM: B[64][1032]bf16 @0 (132096 B), A stages 2x[64][136]bf16 @132096.
// ---------------------------------------------------------------------------
#define BPADE 1032
#define APADE 136
#define SMEM_A0 132096
#define SMEM_LSTM (132096 + 2 * 17408)

__global__ __launch_bounds__(256, 1) void lstm_hmma() {
    extern __shared__ char smem[];
    const int tid = threadIdx.x;
    const int wid = tid >> 5;
    const int lane = tid & 31;
    const int wm = wid & 3;            // M16 row block
    const int wn = wid >> 2;           // N32 col block
    const int lr = lane & 15;
    const int khalf = lane >> 4;
    const int qp = lane >> 2;
    const int t4 = lane & 3;

    const int bm = blockIdx.x >> 5;    // 0..3
    const int bn = blockIdx.x & 31;    // 0..31
    const int m0 = bm << 6;
    const int j0 = bn << 4;

    const uint32_t bB32 = smem_u32(smem);
    const uint32_t aB32_0 = bB32 + SMEM_A0;
    const uint32_t aB32_1 = aB32_0 + 17408;

    // ---- fill resident weights: smem row n <- Wh row gate*512 + j0 + hidl
    for (int u = tid; u < 8192; u += 256) {
        int n = u >> 7, q = u & 127;
        int k0 = q * 8;
        int gate = (n >> 3) & 3;
        int hidl = ((n >> 5) << 3) + (n & 7);
        int gcol = (gate << 9) + j0 + hidl;
        const __nv_bfloat16* src = (k0 < 512) ? (g_W1 + (size_t)gcol * HH + k0)
                                              : (g_W2 + (size_t)gcol * HH + k0 - 512);
        *(uint4*)(smem + ((size_t)n * BPADE + k0) * 2) = *(const uint4*)src;
    }
    __syncthreads();

    // per-thread epilogue coordinates
    const int r0 = m0 + wm * 16 + qp;      // rows r0, r0+8
    const int hid = j0 + wn * 8 + 2 * t4;  // hids hid, hid+1

    float c_st[4] = {0.f, 0.f, 0.f, 0.f};

    for (int t = 0; t < TT; ++t) {
        const int rb = t & 1;
        const __nv_bfloat16* hb = g_hsplit[rb];

        float acc[4][4] = {};          // [gate][d0..d3]
        uint4 pf[4];
        float xv[4][4];                // [gate][d]

        // load A chunk 0
#pragma unroll
        for (int j = 0; j < 4; j++) {
            int u = tid + j * 256;
            int n = u >> 4, q = u & 15;
            pf[j] = __ldcg((const uint4*)(hb + (size_t)(m0 + n) * 1024 + q * 8));
        }
#pragma unroll
        for (int j = 0; j < 4; j++) {
            int u = tid + j * 256;
            int n = u >> 4, q = u & 15;
            *(uint4*)(smem + SMEM_A0 + ((size_t)n * APADE + q * 8) * 2) = pf[j];
        }
        __syncthreads();

        for (int s = 0; s < 8; s++) {
            const uint32_t aCur = (s & 1) ? aB32_1 : aB32_0;
            if (s < 7) {
                // prefetch next A chunk (hsplit chunk s+1)
#pragma unroll
                for (int j = 0; j < 4; j++) {
                    int u = tid + j * 256;
                    int n = u >> 4, q = u & 15;
                    pf[j] = __ldcg((const uint4*)(hb + (size_t)(m0 + n) * 1024
                                                  + (s + 1) * 128 + q * 8));
                }
            } else {
                // load xg[t] operands into registers
#pragma unroll
                for (int g = 0; g < 4; g++) {
                    const float* x0 = g_xg + ((size_t)t * BB + r0) * GG + (g << 9) + hid;
                    const float* x1 = g_xg + ((size_t)t * BB + r0 + 8) * GG + (g << 9) + hid;
                    float2 v0 = __ldcg((const float2*)x0);
                    float2 v1 = __ldcg((const float2*)x1);
                    xv[g][0] = v0.x; xv[g][1] = v0.y;
                    xv[g][2] = v1.x; xv[g][3] = v1.y;
                }
            }

            // compute passes for this A chunk
            const int npass = (s < 4) ? 2 : 1;
#pragma unroll
            for (int pp = 0; pp < 2; pp++) {
                if (pp >= npass) break;
                // B k-offset (bf16 elems): s<4: pass0 W1 chunk s, pass1 W2 chunk s
                //                          s>=4: W1 chunk s-4
                const int kb = (s < 4) ? (pp == 0 ? s * 128 : 512 + s * 128)
                                       : (s - 4) * 128;
#pragma unroll
                for (int k16 = 0; k16 < 8; k16++) {
                    uint32_t a0, a1, a2, a3;
                    uint32_t aAddr = aCur + ((wm * 16 + lr) * APADE + k16 * 16) * 2 + khalf * 16;
                    ldsm4(a0, a1, a2, a3, aAddr);
#pragma unroll
                    for (int p = 0; p < 2; p++) {
                        uint32_t b0, b1, b2, b3;
                        uint32_t bAddr = bB32 + ((uint32_t)(wn * 32 + p * 16 + lr) * BPADE
                                                 + kb + k16 * 16) * 2 + khalf * 16;
                        ldsm4(b0, b1, b2, b3, bAddr);   // NON-trans: [n][k] rows pack k-adjacent
                        mma_bf16(acc[2 * p],     a0, a1, a2, a3, b0, b2);
                        mma_bf16(acc[2 * p + 1], a0, a1, a2, a3, b1, b3);
                    }
                }
            }

            if (s < 7) {
                const uint32_t aNxt = (s & 1) ? aB32_0 : aB32_1;
#pragma unroll
                for (int j = 0; j < 4; j++) {
                    int u = tid + j * 256;
                    int n = u >> 4, q = u & 15;
                    *(uint4*)(smem + (aNxt - bB32) + ((size_t)n * APADE + q * 8) * 2) = pf[j];
                }
                __syncthreads();
            }
        }

        // ---- pointwise in registers: 4 cells (2 rows x 2 hids)
        float hv[4];
#pragma unroll
        for (int d = 0; d < 4; d++) {
            float gi = acc[0][d] + xv[0][d];
            float gf = acc[1][d] + xv[1][d];
            float gg = acc[2][d] + xv[2][d];
            float go = acc[3][d] + xv[3][d];
            float iv = sigm(gi), fv = sigm(gf), gv = tanh_fast(gg), ov = sigm(go);
            float cc = c_st[d] * fv + iv * gv;
            c_st[d] = cc;
            hv[d] = ov * tanh_fast(cc);
        }

        // store bf16 split for next step (+ fp32 h on last step)
        __nv_bfloat16* hs = g_hsplit[rb ^ 1];
#pragma unroll
        for (int rr = 0; rr < 2; rr++) {
            int row = r0 + rr * 8;
            float h0 = hv[rr * 2], h1 = hv[rr * 2 + 1];
            __nv_bfloat16 p0 = __float2bfloat16(h0);
            __nv_bfloat16 p1 = __float2bfloat16(h1);
            __nv_bfloat16 q0 = __float2bfloat16(h0 - __bfloat162float(p0));
            __nv_bfloat16 q1 = __float2bfloat16(h1 - __bfloat162float(p1));
            *(__nv_bfloat162*)(hs + (size_t)row * 1024 + hid)       = __halves2bfloat162(p0, p1);
            *(__nv_bfloat162*)(hs + (size_t)row * 1024 + 512 + hid) = __halves2bfloat162(q0, q1);
            if (t == TT - 1)
                *(float2*)(g_hfp + (size_t)row * HH + hid) = make_float2(h0, h1);
        }

        __threadfence();
        grid_bar(t);
    }
}

// ---------------------------------------------------------------------------
__global__ __launch_bounds__(256) void fc_kernel(const float* __restrict__ Wfc,
                                                 const float* __restrict__ bfc,
                                                 float* __restrict__ out) {
    int warp = (blockIdx.x * blockDim.x + threadIdx.x) >> 5;
    int lane = threadIdx.x & 31;
    if (warp >= BB * OO) return;
    int b = warp / OO;
    int o = warp - b * OO;
    const float4* hr = reinterpret_cast<const float4*>(g_hfp + (size_t)b * HH);
    const float4* wr = reinterpret_cast<const float4*>(Wfc + (size_t)o * HH);
    float s = 0.0f;
#pragma unroll
    for (int k = 0; k < 4; k++) {
        float4 h4 = hr[lane + (k << 5)];
        float4 w4 = wr[lane + (k << 5)];
        s += h4.x * w4.x + h4.y * w4.y + h4.z * w4.z + h4.w * w4.w;
    }
#pragma unroll
    for (int off = 16; off; off >>= 1) s += __shfl_xor_sync(0xffffffffu, s, off);
    if (lane == 0) out[warp] = s + bfc[o];
}

// ---------------------------------------------------------------------------
extern "C" void kernel_launch(void* const* d_in, const int* in_sizes, int n_in,
                              void* d_out, int out_size) {
    const float* x   = (const float*)d_in[0];
    const float* Wx  = (const float*)d_in[1];
    const float* bx  = (const float*)d_in[2];
    const float* Wh  = (const float*)d_in[3];
    const float* bh  = (const float*)d_in[4];
    const float* Wfc = (const float*)d_in[5];
    const float* bfc = (const float*)d_in[6];
    float* out = (float*)d_out;

    prep_kernel<<<256, 256>>>(Wh);

    {
        dim3 grid((TT * BB) / 128, GG / 128);   // (1000, 16)
        xg_gemm<<<grid, 256>>>(x, Wx, bx, bh);
    }

    cudaFuncSetAttribute(lstm_hmma, cudaFuncAttributeMaxDynamicSharedMemorySize, SMEM_LSTM);
    lstm_hmma<<<NBLK, 256, SMEM_LSTM>>>();

    fc_kernel<<<(BB * OO * 32 + 255) / 256, 256>>>(Wfc, bfc, out);
}

// round 9
// speedup vs baseline: 2.5450x; 1.2637x over previous
#include <cuda_runtime.h>
#include <cuda_bf16.h>
#include <math.h>
#include <cstdint>

#define BB 256
#define TT 500
#define II 256
#define HH 512
#define GG 2048
#define OO 100
#define NBLK 128

typedef unsigned long long ull;

// ------------------------- global scratch (no allocs) -----------------------
__device__ float g_xg[(size_t)TT * BB * GG];            // [T][B][4H]
__device__ __nv_bfloat16 g_xs[(size_t)TT * BB * 512];   // [t*B+b][k]: k<256 x1, >=256 x2
__device__ __nv_bfloat16 g_Wxs[GG * 512];               // [n][k]: k<256 Wx1, >=256 Wx2
__device__ __nv_bfloat16 g_hsplit[2][BB * 1024];        // [buf][b][k]: k<512 h1, >=512 h2
__device__ float g_hfp[BB * HH];                        // fp32 h (for fc)
__device__ __nv_bfloat16 g_W1[GG * HH];                 // bf16(Wh)
__device__ __nv_bfloat16 g_W2[GG * HH];                 // bf16(Wh - W1)
__device__ unsigned g_bar_count;
__device__ volatile unsigned g_epoch;

// ------------------------- helpers ------------------------------------------
__device__ __forceinline__ float sigm(float x) { return 1.0f / (1.0f + __expf(-x)); }
__device__ __forceinline__ float tanh_fast(float x) { return 1.0f - 2.0f / (1.0f + __expf(2.0f * x)); }
__device__ __forceinline__ uint32_t smem_u32(const void* p) {
    return (uint32_t)__cvta_generic_to_shared(p);
}
__device__ __forceinline__ void ldsm4(uint32_t& a0, uint32_t& a1, uint32_t& a2, uint32_t& a3,
                                      uint32_t addr) {
    asm volatile("ldmatrix.sync.aligned.m8n8.x4.shared.b16 {%0,%1,%2,%3}, [%4];"
                 : "=r"(a0), "=r"(a1), "=r"(a2), "=r"(a3) : "r"(addr));
}
__device__ __forceinline__ void mma_bf16(float* d, uint32_t a0, uint32_t a1, uint32_t a2,
                                         uint32_t a3, uint32_t b0, uint32_t b1) {
    asm volatile(
        "mma.sync.aligned.m16n8k16.row.col.f32.bf16.bf16.f32 "
        "{%0,%1,%2,%3}, {%4,%5,%6,%7}, {%8,%9}, {%0,%1,%2,%3};"
        : "+f"(d[0]), "+f"(d[1]), "+f"(d[2]), "+f"(d[3])
        : "r"(a0), "r"(a1), "r"(a2), "r"(a3), "r"(b0), "r"(b1));
}
__device__ __forceinline__ __nv_bfloat162 split_hi(float a, float b, float& ra, float& rb) {
    __nv_bfloat16 p = __float2bfloat16(a);
    __nv_bfloat16 q = __float2bfloat16(b);
    ra = a - __bfloat162float(p);
    rb = b - __bfloat162float(q);
    return __halves2bfloat162(p, q);
}

// ---------------------------------------------------------------------------
// Prep A: split x into g_xs (transposed to [t*B+b] row order)
// ---------------------------------------------------------------------------
__global__ __launch_bounds__(256) void xsplit_kernel(const float* __restrict__ x) {
    const int total = TT * BB * 64;           // one float4 (4 k) per thread-iter
    const int stride = gridDim.x * blockDim.x;
    for (int idx = blockIdx.x * blockDim.x + threadIdx.x; idx < total; idx += stride) {
        int r = idx >> 6;                     // row = t*BB + b
        int q = idx & 63;                     // k/4
        int t = r >> 8;
        int b = r & 255;
        float4 v = *(const float4*)(x + ((size_t)b * TT + t) * II + q * 4);
        float r0, r1, r2, r3;
        __nv_bfloat162 h01, h23;
        {
            __nv_bfloat16 p0 = __float2bfloat16(v.x), p1 = __float2bfloat16(v.y);
            __nv_bfloat16 p2 = __float2bfloat16(v.z), p3 = __float2bfloat16(v.w);
            r0 = v.x - __bfloat162float(p0); r1 = v.y - __bfloat162float(p1);
            r2 = v.z - __bfloat162float(p2); r3 = v.w - __bfloat162float(p3);
            h01 = __halves2bfloat162(p0, p1); h23 = __halves2bfloat162(p2, p3);
        }
        __nv_bfloat16* row = g_xs + (size_t)r * 512;
        *(__nv_bfloat162*)(row + q * 4)     = h01;
        *(__nv_bfloat162*)(row + q * 4 + 2) = h23;
        *(__nv_bfloat162*)(row + 256 + q * 4)     = __halves2bfloat162(__float2bfloat16(r0), __float2bfloat16(r1));
        *(__nv_bfloat162*)(row + 256 + q * 4 + 2) = __halves2bfloat162(__float2bfloat16(r2), __float2bfloat16(r3));
    }
}

// ---------------------------------------------------------------------------
// Prep B: split Wh -> g_W1/g_W2, Wx -> g_Wxs; zero h buffers; reset barrier
// ---------------------------------------------------------------------------
__global__ __launch_bounds__(256) void prep_kernel(const float* __restrict__ Wh,
                                                   const float* __restrict__ Wx) {
    int stride = gridDim.x * blockDim.x;
    for (int idx = blockIdx.x * blockDim.x + threadIdx.x; idx < GG * HH; idx += stride) {
        float w = Wh[idx];
        __nv_bfloat16 w1 = __float2bfloat16(w);
        g_W1[idx] = w1;
        g_W2[idx] = __float2bfloat16(w - __bfloat162float(w1));
    }
    for (int idx = blockIdx.x * blockDim.x + threadIdx.x; idx < GG * II; idx += stride) {
        int n = idx >> 8, k = idx & 255;
        float w = Wx[idx];
        __nv_bfloat16 w1 = __float2bfloat16(w);
        g_Wxs[(size_t)n * 512 + k] = w1;
        g_Wxs[(size_t)n * 512 + 256 + k] = __float2bfloat16(w - __bfloat162float(w1));
    }
    __nv_bfloat16 z = __float2bfloat16(0.0f);
    for (int idx = blockIdx.x * blockDim.x + threadIdx.x; idx < BB * 1024; idx += stride) {
        g_hsplit[0][idx] = z;
        g_hsplit[1][idx] = z;
    }
    if (blockIdx.x == 0 && threadIdx.x == 0) { g_bar_count = 0; g_epoch = 0; }
}

// ---------------------------------------------------------------------------
// Kernel 1: xg = x @ Wx^T + bx + bh via HMMA 3-term split.
// Tile 128x128, 256 thr (8 warps: wm 0..3 -> M32, wn 0..1 -> N64).
// K chunks: 12 x 64 (pass 0: x1*W1, 1: x2*W1, 2: x1*W2).
// SMEM (dynamic): A[2][128][72]bf16, B[2][128][72]bf16 = 73728 B.
// ---------------------------------------------------------------------------
#define XPAD 72
#define XCHUNK (128 * XPAD * 2)              // 18432 B per stage
#define SMEM_XG (4 * XCHUNK)

__global__ __launch_bounds__(256, 1) void xg_hmma(const float* __restrict__ bx,
                                                  const float* __restrict__ bh) {
    extern __shared__ char smem[];
    const int tid = threadIdx.x;
    const int wid = tid >> 5;
    const int lane = tid & 31;
    const int wm = wid & 3;                  // M32 block
    const int wn = wid >> 2;                 // N64 block
    const int lr = lane & 15;
    const int khalf = lane >> 4;
    const int qp = lane >> 2;
    const int t4 = lane & 3;

    const size_t mBase = (size_t)blockIdx.x * 128;
    const int nBase = blockIdx.y * 128;

    const uint32_t aS[2] = { smem_u32(smem), smem_u32(smem) + XCHUNK };
    const uint32_t bS[2] = { aS[0] + 2 * XCHUNK, aS[0] + 3 * XCHUNK };

    // staging mapping: 4 uint4 per thread per operand
    const int rn = tid >> 1;                 // rows rn, rn+128? no: u = tid + j*256
    (void)rn;

    // bias for this thread's 16 output cols
    float2 biasv[8];
#pragma unroll
    for (int nb = 0; nb < 8; nb++) {
        int col = nBase + wn * 64 + nb * 8 + 2 * t4;
        biasv[nb] = make_float2(bx[col] + bh[col], bx[col + 1] + bh[col + 1]);
    }

    float acc[2][8][4] = {};
    uint4 pfA[4], pfB[4];

    // chunk parameters
    auto aCol = [](int c) { return ((c >> 2) == 1 ? 256 : 0) + (c & 3) * 64; };
    auto bCol = [](int c) { return ((c >> 2) == 2 ? 256 : 0) + (c & 3) * 64; };

    // load chunk 0
#pragma unroll
    for (int j = 0; j < 4; j++) {
        int u = tid + j * 256;
        int n = u >> 3, q = u & 7;
        pfA[j] = *(const uint4*)(g_xs + (mBase + n) * 512 + aCol(0) + q * 8);
        pfB[j] = *(const uint4*)(g_Wxs + (size_t)(nBase + n) * 512 + bCol(0) + q * 8);
    }
#pragma unroll
    for (int j = 0; j < 4; j++) {
        int u = tid + j * 256;
        int n = u >> 3, q = u & 7;
        *(uint4*)(smem + (size_t)n * (XPAD * 2) + q * 16) = pfA[j];
        *(uint4*)(smem + 2 * XCHUNK + (size_t)n * (XPAD * 2) + q * 16) = pfB[j];
    }
    __syncthreads();

    for (int c = 0; c < 12; c++) {
        const int st = c & 1;
        if (c < 11) {
#pragma unroll
            for (int j = 0; j < 4; j++) {
                int u = tid + j * 256;
                int n = u >> 3, q = u & 7;
                pfA[j] = *(const uint4*)(g_xs + (mBase + n) * 512 + aCol(c + 1) + q * 8);
                pfB[j] = *(const uint4*)(g_Wxs + (size_t)(nBase + n) * 512 + bCol(c + 1) + q * 8);
            }
        }
#pragma unroll
        for (int k16 = 0; k16 < 4; k16++) {
            uint32_t a[2][4];
#pragma unroll
            for (int mi = 0; mi < 2; mi++) {
                uint32_t addr = aS[st] + (uint32_t)(wm * 32 + mi * 16 + lr) * (XPAD * 2)
                                + k16 * 32 + khalf * 16;
                ldsm4(a[mi][0], a[mi][1], a[mi][2], a[mi][3], addr);
            }
#pragma unroll
            for (int p = 0; p < 4; p++) {
                uint32_t b0, b1, b2, b3;
                uint32_t addr = bS[st] + (uint32_t)(wn * 64 + p * 16 + lr) * (XPAD * 2)
                                + k16 * 32 + khalf * 16;
                ldsm4(b0, b1, b2, b3, addr);
#pragma unroll
                for (int mi = 0; mi < 2; mi++) {
                    mma_bf16(acc[mi][2 * p],     a[mi][0], a[mi][1], a[mi][2], a[mi][3], b0, b2);
                    mma_bf16(acc[mi][2 * p + 1], a[mi][0], a[mi][1], a[mi][2], a[mi][3], b1, b3);
                }
            }
        }
        if (c < 11) {
            const int ns = (c + 1) & 1;
#pragma unroll
            for (int j = 0; j < 4; j++) {
                int u = tid + j * 256;
                int n = u >> 3, q = u & 7;
                *(uint4*)(smem + (size_t)ns * XCHUNK + (size_t)n * (XPAD * 2) + q * 16) = pfA[j];
                *(uint4*)(smem + 2 * XCHUNK + (size_t)ns * XCHUNK + (size_t)n * (XPAD * 2) + q * 16) = pfB[j];
            }
            __syncthreads();
        }
    }

    // epilogue: bias add + store
#pragma unroll
    for (int mi = 0; mi < 2; mi++) {
#pragma unroll
        for (int rr = 0; rr < 2; rr++) {
            size_t row = mBase + wm * 32 + mi * 16 + qp + rr * 8;
            float* orow = g_xg + row * GG + nBase + wn * 64;
#pragma unroll
            for (int nb = 0; nb < 8; nb++) {
                float2 o = make_float2(acc[mi][nb][2 * rr] + biasv[nb].x,
                                       acc[mi][nb][2 * rr + 1] + biasv[nb].y);
                *(float2*)(orow + nb * 8 + 2 * t4) = o;
            }
        }
    }
}

// ---------------------------------------------------------------------------
__device__ __forceinline__ void grid_bar(unsigned ep) {
    __syncthreads();
    if (threadIdx.x == 0) {
        unsigned arrived = atomicAdd(&g_bar_count, 1);
        if (arrived == NBLK - 1) {
            g_bar_count = 0;
            __threadfence();
            g_epoch = ep + 1;
        } else {
            while (g_epoch <= ep) __nanosleep(32);
            __threadfence();
        }
    }
    __syncthreads();
}

// ---------------------------------------------------------------------------
// Kernel 2: persistent HMMA LSTM recurrence (unchanged from round 8, PASS)
// ---------------------------------------------------------------------------
#define BPADE 1032
#define APADE 136
#define SMEM_A0 132096
#define SMEM_LSTM (132096 + 2 * 17408)

__global__ __launch_bounds__(256, 1) void lstm_hmma() {
    extern __shared__ char smem[];
    const int tid = threadIdx.x;
    const int wid = tid >> 5;
    const int lane = tid & 31;
    const int wm = wid & 3;
    const int wn = wid >> 2;
    const int lr = lane & 15;
    const int khalf = lane >> 4;
    const int qp = lane >> 2;
    const int t4 = lane & 3;

    const int bm = blockIdx.x >> 5;
    const int bn = blockIdx.x & 31;
    const int m0 = bm << 6;
    const int j0 = bn << 4;

    const uint32_t bB32 = smem_u32(smem);
    const uint32_t aB32_0 = bB32 + SMEM_A0;
    const uint32_t aB32_1 = aB32_0 + 17408;

    for (int u = tid; u < 8192; u += 256) {
        int n = u >> 7, q = u & 127;
        int k0 = q * 8;
        int gate = (n >> 3) & 3;
        int hidl = ((n >> 5) << 3) + (n & 7);
        int gcol = (gate << 9) + j0 + hidl;
        const __nv_bfloat16* src = (k0 < 512) ? (g_W1 + (size_t)gcol * HH + k0)
                                              : (g_W2 + (size_t)gcol * HH + k0 - 512);
        *(uint4*)(smem + ((size_t)n * BPADE + k0) * 2) = *(const uint4*)src;
    }
    __syncthreads();

    const int r0 = m0 + wm * 16 + qp;
    const int hid = j0 + wn * 8 + 2 * t4;

    float c_st[4] = {0.f, 0.f, 0.f, 0.f};

    for (int t = 0; t < TT; ++t) {
        const int rb = t & 1;
        const __nv_bfloat16* hb = g_hsplit[rb];

        float acc[4][4] = {};
        uint4 pf[4];
        float xv[4][4];

#pragma unroll
        for (int j = 0; j < 4; j++) {
            int u = tid + j * 256;
            int n = u >> 4, q = u & 15;
            pf[j] = __ldcg((const uint4*)(hb + (size_t)(m0 + n) * 1024 + q * 8));
        }
#pragma unroll
        for (int j = 0; j < 4; j++) {
            int u = tid + j * 256;
            int n = u >> 4, q = u & 15;
            *(uint4*)(smem + SMEM_A0 + ((size_t)n * APADE + q * 8) * 2) = pf[j];
        }
        __syncthreads();

        for (int s = 0; s < 8; s++) {
            const uint32_t aCur = (s & 1) ? aB32_1 : aB32_0;
            if (s < 7) {
#pragma unroll
                for (int j = 0; j < 4; j++) {
                    int u = tid + j * 256;
                    int n = u >> 4, q = u & 15;
                    pf[j] = __ldcg((const uint4*)(hb + (size_t)(m0 + n) * 1024
                                                  + (s + 1) * 128 + q * 8));
                }
            } else {
#pragma unroll
                for (int g = 0; g < 4; g++) {
                    const float* x0 = g_xg + ((size_t)t * BB + r0) * GG + (g << 9) + hid;
                    const float* x1 = g_xg + ((size_t)t * BB + r0 + 8) * GG + (g << 9) + hid;
                    float2 v0 = __ldcg((const float2*)x0);
                    float2 v1 = __ldcg((const float2*)x1);
                    xv[g][0] = v0.x; xv[g][1] = v0.y;
                    xv[g][2] = v1.x; xv[g][3] = v1.y;
                }
            }

            const int npass = (s < 4) ? 2 : 1;
#pragma unroll
            for (int pp = 0; pp < 2; pp++) {
                if (pp >= npass) break;
                const int kb = (s < 4) ? (pp == 0 ? s * 128 : 512 + s * 128)
                                       : (s - 4) * 128;
#pragma unroll
                for (int k16 = 0; k16 < 8; k16++) {
                    uint32_t a0, a1, a2, a3;
                    uint32_t aAddr = aCur + ((wm * 16 + lr) * APADE + k16 * 16) * 2 + khalf * 16;
                    ldsm4(a0, a1, a2, a3, aAddr);
#pragma unroll
                    for (int p = 0; p < 2; p++) {
                        uint32_t b0, b1, b2, b3;
                        uint32_t bAddr = bB32 + ((uint32_t)(wn * 32 + p * 16 + lr) * BPADE
                                                 + kb + k16 * 16) * 2 + khalf * 16;
                        ldsm4(b0, b1, b2, b3, bAddr);
                        mma_bf16(acc[2 * p],     a0, a1, a2, a3, b0, b2);
                        mma_bf16(acc[2 * p + 1], a0, a1, a2, a3, b1, b3);
                    }
                }
            }

            if (s < 7) {
                const uint32_t aNxt = (s & 1) ? aB32_0 : aB32_1;
#pragma unroll
                for (int j = 0; j < 4; j++) {
                    int u = tid + j * 256;
                    int n = u >> 4, q = u & 15;
                    *(uint4*)(smem + (aNxt - bB32) + ((size_t)n * APADE + q * 8) * 2) = pf[j];
                }
                __syncthreads();
            }
        }

        float hv[4];
#pragma unroll
        for (int d = 0; d < 4; d++) {
            float gi = acc[0][d] + xv[0][d];
            float gf = acc[1][d] + xv[1][d];
            float gg = acc[2][d] + xv[2][d];
            float go = acc[3][d] + xv[3][d];
            float iv = sigm(gi), fv = sigm(gf), gv = tanh_fast(gg), ov = sigm(go);
            float cc = c_st[d] * fv + iv * gv;
            c_st[d] = cc;
            hv[d] = ov * tanh_fast(cc);
        }

        __nv_bfloat16* hs = g_hsplit[rb ^ 1];
#pragma unroll
        for (int rr = 0; rr < 2; rr++) {
            int row = r0 + rr * 8;
            float h0 = hv[rr * 2], h1 = hv[rr * 2 + 1];
            __nv_bfloat16 p0 = __float2bfloat16(h0);
            __nv_bfloat16 p1 = __float2bfloat16(h1);
            __nv_bfloat16 q0 = __float2bfloat16(h0 - __bfloat162float(p0));
            __nv_bfloat16 q1 = __float2bfloat16(h1 - __bfloat162float(p1));
            *(__nv_bfloat162*)(hs + (size_t)row * 1024 + hid)       = __halves2bfloat162(p0, p1);
            *(__nv_bfloat162*)(hs + (size_t)row * 1024 + 512 + hid) = __halves2bfloat162(q0, q1);
            if (t == TT - 1)
                *(float2*)(g_hfp + (size_t)row * HH + hid) = make_float2(h0, h1);
        }

        __threadfence();
        grid_bar(t);
    }
}

// ---------------------------------------------------------------------------
__global__ __launch_bounds__(256) void fc_kernel(const float* __restrict__ Wfc,
                                                 const float* __restrict__ bfc,
                                                 float* __restrict__ out) {
    int warp = (blockIdx.x * blockDim.x + threadIdx.x) >> 5;
    int lane = threadIdx.x & 31;
    if (warp >= BB * OO) return;
    int b = warp / OO;
    int o = warp - b * OO;
    const float4* hr = reinterpret_cast<const float4*>(g_hfp + (size_t)b * HH);
    const float4* wr = reinterpret_cast<const float4*>(Wfc + (size_t)o * HH);
    float s = 0.0f;
#pragma unroll
    for (int k = 0; k < 4; k++) {
        float4 h4 = hr[lane + (k << 5)];
        float4 w4 = wr[lane + (k << 5)];
        s += h4.x * w4.x + h4.y * w4.y + h4.z * w4.z + h4.w * w4.w;
    }
#pragma unroll
    for (int off = 16; off; off >>= 1) s += __shfl_xor_sync(0xffffffffu, s, off);
    if (lane == 0) out[warp] = s + bfc[o];
}

// ---------------------------------------------------------------------------
extern "C" void kernel_launch(void* const* d_in, const int* in_sizes, int n_in,
                              void* d_out, int out_size) {
    const float* x   = (const float*)d_in[0];
    const float* Wx  = (const float*)d_in[1];
    const float* bx  = (const float*)d_in[2];
    const float* Wh  = (const float*)d_in[3];
    const float* bh  = (const float*)d_in[4];
    const float* Wfc = (const float*)d_in[5];
    const float* bfc = (const float*)d_in[6];
    float* out = (float*)d_out;

    prep_kernel<<<256, 256>>>(Wh, Wx);
    xsplit_kernel<<<2048, 256>>>(x);

    {
        dim3 grid((TT * BB) / 128, GG / 128);   // (1000, 16)
        cudaFuncSetAttribute(xg_hmma, cudaFuncAttributeMaxDynamicSharedMemorySize, SMEM_XG);
        xg_hmma<<<grid, 256, SMEM_XG>>>(bx, bh);
    }

    cudaFuncSetAttribute(lstm_hmma, cudaFuncAttributeMaxDynamicSharedMemorySize, SMEM_LSTM);
    lstm_hmma<<<NBLK, 256, SMEM_LSTM>>>();

    fc_kernel<<<(BB * OO * 32 + 255) / 256, 256>>>(Wfc, bfc, out);
}

// round 10
// speedup vs baseline: 2.6779x; 1.0522x over previous
#include <cuda_runtime.h>
#include <cuda_bf16.h>
#include <math.h>
#include <cstdint>

#define BB 256
#define TT 500
#define II 256
#define HH 512
#define GG 2048
#define OO 100
#define NBLK 128

typedef unsigned long long ull;

// ------------------------- global scratch (no allocs) -----------------------
__device__ float g_xg[(size_t)TT * BB * GG];            // [T][B][4H]
__device__ __nv_bfloat16 g_xs[(size_t)TT * BB * 512];   // [t*B+b][k]: k<256 x1, >=256 x2
__device__ __nv_bfloat16 g_Wxs[GG * 512];               // [n][k]: k<256 Wx1, >=256 Wx2
__device__ __nv_bfloat16 g_hsplit[2][BB * 1024];        // [buf][b][k]: k<512 h1, >=512 h2
__device__ float g_hfp[BB * HH];                        // fp32 h (for fc)
__device__ __nv_bfloat16 g_W1[GG * HH];                 // bf16(Wh)
__device__ __nv_bfloat16 g_W2[GG * HH];                 // bf16(Wh - W1)
__device__ unsigned g_bar_count;
__device__ volatile unsigned g_epoch;

// ------------------------- helpers ------------------------------------------
__device__ __forceinline__ float sigm(float x) { return 1.0f / (1.0f + __expf(-x)); }
__device__ __forceinline__ float tanh_fast(float x) { return 1.0f - 2.0f / (1.0f + __expf(2.0f * x)); }
__device__ __forceinline__ uint32_t smem_u32(const void* p) {
    return (uint32_t)__cvta_generic_to_shared(p);
}
__device__ __forceinline__ void ldsm4(uint32_t& a0, uint32_t& a1, uint32_t& a2, uint32_t& a3,
                                      uint32_t addr) {
    asm volatile("ldmatrix.sync.aligned.m8n8.x4.shared.b16 {%0,%1,%2,%3}, [%4];"
                 : "=r"(a0), "=r"(a1), "=r"(a2), "=r"(a3) : "r"(addr));
}
__device__ __forceinline__ void mma_bf16(float* d, uint32_t a0, uint32_t a1, uint32_t a2,
                                         uint32_t a3, uint32_t b0, uint32_t b1) {
    asm volatile(
        "mma.sync.aligned.m16n8k16.row.col.f32.bf16.bf16.f32 "
        "{%0,%1,%2,%3}, {%4,%5,%6,%7}, {%8,%9}, {%0,%1,%2,%3};"
        : "+f"(d[0]), "+f"(d[1]), "+f"(d[2]), "+f"(d[3])
        : "r"(a0), "r"(a1), "r"(a2), "r"(a3), "r"(b0), "r"(b1));
}

// ---------------------------------------------------------------------------
// Prep A: split x into g_xs (transposed to [t*B+b] row order)
// ---------------------------------------------------------------------------
__global__ __launch_bounds__(256) void xsplit_kernel(const float* __restrict__ x) {
    const int total = TT * BB * 64;
    const int stride = gridDim.x * blockDim.x;
    for (int idx = blockIdx.x * blockDim.x + threadIdx.x; idx < total; idx += stride) {
        int r = idx >> 6;
        int q = idx & 63;
        int t = r >> 8;
        int b = r & 255;
        float4 v = *(const float4*)(x + ((size_t)b * TT + t) * II + q * 4);
        float r0, r1, r2, r3;
        __nv_bfloat162 h01, h23;
        {
            __nv_bfloat16 p0 = __float2bfloat16(v.x), p1 = __float2bfloat16(v.y);
            __nv_bfloat16 p2 = __float2bfloat16(v.z), p3 = __float2bfloat16(v.w);
            r0 = v.x - __bfloat162float(p0); r1 = v.y - __bfloat162float(p1);
            r2 = v.z - __bfloat162float(p2); r3 = v.w - __bfloat162float(p3);
            h01 = __halves2bfloat162(p0, p1); h23 = __halves2bfloat162(p2, p3);
        }
        __nv_bfloat16* row = g_xs + (size_t)r * 512;
        *(__nv_bfloat162*)(row + q * 4)     = h01;
        *(__nv_bfloat162*)(row + q * 4 + 2) = h23;
        *(__nv_bfloat162*)(row + 256 + q * 4)     = __halves2bfloat162(__float2bfloat16(r0), __float2bfloat16(r1));
        *(__nv_bfloat162*)(row + 256 + q * 4 + 2) = __halves2bfloat162(__float2bfloat16(r2), __float2bfloat16(r3));
    }
}

// ---------------------------------------------------------------------------
// Prep B: split Wh -> g_W1/g_W2, Wx -> g_Wxs; zero h buffers; reset barrier
// ---------------------------------------------------------------------------
__global__ __launch_bounds__(256) void prep_kernel(const float* __restrict__ Wh,
                                                   const float* __restrict__ Wx) {
    int stride = gridDim.x * blockDim.x;
    for (int idx = blockIdx.x * blockDim.x + threadIdx.x; idx < GG * HH; idx += stride) {
        float w = Wh[idx];
        __nv_bfloat16 w1 = __float2bfloat16(w);
        g_W1[idx] = w1;
        g_W2[idx] = __float2bfloat16(w - __bfloat162float(w1));
    }
    for (int idx = blockIdx.x * blockDim.x + threadIdx.x; idx < GG * II; idx += stride) {
        int n = idx >> 8, k = idx & 255;
        float w = Wx[idx];
        __nv_bfloat16 w1 = __float2bfloat16(w);
        g_Wxs[(size_t)n * 512 + k] = w1;
        g_Wxs[(size_t)n * 512 + 256 + k] = __float2bfloat16(w - __bfloat162float(w1));
    }
    __nv_bfloat16 z = __float2bfloat16(0.0f);
    for (int idx = blockIdx.x * blockDim.x + threadIdx.x; idx < BB * 1024; idx += stride) {
        g_hsplit[0][idx] = z;
        g_hsplit[1][idx] = z;
    }
    if (blockIdx.x == 0 && threadIdx.x == 0) { g_bar_count = 0; g_epoch = 0; }
}

// ---------------------------------------------------------------------------
// Kernel 1: xg = x @ Wx^T + bx + bh via HMMA 3-term split (round-9, PASS)
// ---------------------------------------------------------------------------
#define XPAD 72
#define XCHUNK (128 * XPAD * 2)
#define SMEM_XG (4 * XCHUNK)

__global__ __launch_bounds__(256, 1) void xg_hmma(const float* __restrict__ bx,
                                                  const float* __restrict__ bh) {
    extern __shared__ char smem[];
    const int tid = threadIdx.x;
    const int wid = tid >> 5;
    const int lane = tid & 31;
    const int wm = wid & 3;
    const int wn = wid >> 2;
    const int lr = lane & 15;
    const int khalf = lane >> 4;
    const int qp = lane >> 2;
    const int t4 = lane & 3;

    const size_t mBase = (size_t)blockIdx.x * 128;
    const int nBase = blockIdx.y * 128;

    const uint32_t aS[2] = { smem_u32(smem), smem_u32(smem) + XCHUNK };
    const uint32_t bS[2] = { aS[0] + 2 * XCHUNK, aS[0] + 3 * XCHUNK };

    float2 biasv[8];
#pragma unroll
    for (int nb = 0; nb < 8; nb++) {
        int col = nBase + wn * 64 + nb * 8 + 2 * t4;
        biasv[nb] = make_float2(bx[col] + bh[col], bx[col + 1] + bh[col + 1]);
    }

    float acc[2][8][4] = {};
    uint4 pfA[4], pfB[4];

    auto aCol = [](int c) { return ((c >> 2) == 1 ? 256 : 0) + (c & 3) * 64; };
    auto bCol = [](int c) { return ((c >> 2) == 2 ? 256 : 0) + (c & 3) * 64; };

#pragma unroll
    for (int j = 0; j < 4; j++) {
        int u = tid + j * 256;
        int n = u >> 3, q = u & 7;
        pfA[j] = *(const uint4*)(g_xs + (mBase + n) * 512 + aCol(0) + q * 8);
        pfB[j] = *(const uint4*)(g_Wxs + (size_t)(nBase + n) * 512 + bCol(0) + q * 8);
    }
#pragma unroll
    for (int j = 0; j < 4; j++) {
        int u = tid + j * 256;
        int n = u >> 3, q = u & 7;
        *(uint4*)(smem + (size_t)n * (XPAD * 2) + q * 16) = pfA[j];
        *(uint4*)(smem + 2 * XCHUNK + (size_t)n * (XPAD * 2) + q * 16) = pfB[j];
    }
    __syncthreads();

    for (int c = 0; c < 12; c++) {
        const int st = c & 1;
        if (c < 11) {
#pragma unroll
            for (int j = 0; j < 4; j++) {
                int u = tid + j * 256;
                int n = u >> 3, q = u & 7;
                pfA[j] = *(const uint4*)(g_xs + (mBase + n) * 512 + aCol(c + 1) + q * 8);
                pfB[j] = *(const uint4*)(g_Wxs + (size_t)(nBase + n) * 512 + bCol(c + 1) + q * 8);
            }
        }
#pragma unroll
        for (int k16 = 0; k16 < 4; k16++) {
            uint32_t a[2][4];
#pragma unroll
            for (int mi = 0; mi < 2; mi++) {
                uint32_t addr = aS[st] + (uint32_t)(wm * 32 + mi * 16 + lr) * (XPAD * 2)
                                + k16 * 32 + khalf * 16;
                ldsm4(a[mi][0], a[mi][1], a[mi][2], a[mi][3], addr);
            }
#pragma unroll
            for (int p = 0; p < 4; p++) {
                uint32_t b0, b1, b2, b3;
                uint32_t addr = bS[st] + (uint32_t)(wn * 64 + p * 16 + lr) * (XPAD * 2)
                                + k16 * 32 + khalf * 16;
                ldsm4(b0, b1, b2, b3, addr);
#pragma unroll
                for (int mi = 0; mi < 2; mi++) {
                    mma_bf16(acc[mi][2 * p],     a[mi][0], a[mi][1], a[mi][2], a[mi][3], b0, b2);
                    mma_bf16(acc[mi][2 * p + 1], a[mi][0], a[mi][1], a[mi][2], a[mi][3], b1, b3);
                }
            }
        }
        if (c < 11) {
            const int ns = (c + 1) & 1;
#pragma unroll
            for (int j = 0; j < 4; j++) {
                int u = tid + j * 256;
                int n = u >> 3, q = u & 7;
                *(uint4*)(smem + (size_t)ns * XCHUNK + (size_t)n * (XPAD * 2) + q * 16) = pfA[j];
                *(uint4*)(smem + 2 * XCHUNK + (size_t)ns * XCHUNK + (size_t)n * (XPAD * 2) + q * 16) = pfB[j];
            }
            __syncthreads();
        }
    }

#pragma unroll
    for (int mi = 0; mi < 2; mi++) {
#pragma unroll
        for (int rr = 0; rr < 2; rr++) {
            size_t row = mBase + wm * 32 + mi * 16 + qp + rr * 8;
            float* orow = g_xg + row * GG + nBase + wn * 64;
#pragma unroll
            for (int nb = 0; nb < 8; nb++) {
                float2 o = make_float2(acc[mi][nb][2 * rr] + biasv[nb].x,
                                       acc[mi][nb][2 * rr + 1] + biasv[nb].y);
                *(float2*)(orow + nb * 8 + 2 * t4) = o;
            }
        }
    }
}

// ---------------------------------------------------------------------------
// Fast grid barrier: RED arrivals (no same-address atomic serialization on the
// return path), monotonic counter (no reset race), block 0 publishes epoch.
// ---------------------------------------------------------------------------
__device__ __forceinline__ void grid_bar_fast(unsigned ep) {
    __syncthreads();
    if (threadIdx.x == 0) {
        __threadfence();                 // order h stores before arrival
        atomicAdd(&g_bar_count, 1u);     // result unused -> RED.GLOBAL
        if (blockIdx.x == 0) {
            while (*(volatile unsigned*)&g_bar_count < (ep + 1) * NBLK) {}
            __threadfence();
            g_epoch = ep + 1;
        } else {
            while (g_epoch <= ep) {}
            __threadfence();
        }
    }
    __syncthreads();
}

// ---------------------------------------------------------------------------
// Kernel 2: persistent HMMA LSTM recurrence v2.
// 128 blocks x 256 threads, tile 64 batch x 64 gate-cols.
// Changes vs round 8 (which passed): Bk=256 A-chunks (4 chunks, 3 syncs fewer),
// fused W1/W2 passes reusing A fragments, RED-based grid barrier.
// SMEM: B[64][1032]bf16 @0 (132096 B), A stages 2x[64 x 528B] @132096.
// ---------------------------------------------------------------------------
#define BPADE 1032
#define AST 528
#define ASTAGE 33792
#define SMEM_A0 132096
#define SMEM_LSTM (SMEM_A0 + 2 * ASTAGE)

__global__ __launch_bounds__(256, 1) void lstm_hmma() {
    extern __shared__ char smem[];
    const int tid = threadIdx.x;
    const int lane = tid & 31;
    const int wid = tid >> 5;
    const int wm = wid & 3;
    const int wn = wid >> 2;
    const int lr = lane & 15;
    const int khalf = lane >> 4;
    const int qp = lane >> 2;
    const int t4 = lane & 3;

    const int bm = blockIdx.x >> 5;
    const int bn = blockIdx.x & 31;
    const int m0 = bm << 6;
    const int j0 = bn << 4;

    const uint32_t bB32 = smem_u32(smem);
    const uint32_t aB[2] = { bB32 + SMEM_A0, bB32 + SMEM_A0 + ASTAGE };

    // resident weights: smem row n <- Wh row gate*512 + j0 + hidl (k-major)
    for (int u = tid; u < 8192; u += 256) {
        int n = u >> 7, q = u & 127;
        int k0 = q * 8;
        int gate = (n >> 3) & 3;
        int hidl = ((n >> 5) << 3) + (n & 7);
        int gcol = (gate << 9) + j0 + hidl;
        const __nv_bfloat16* src = (k0 < 512) ? (g_W1 + (size_t)gcol * HH + k0)
                                              : (g_W2 + (size_t)gcol * HH + k0 - 512);
        *(uint4*)(smem + ((size_t)n * BPADE + k0) * 2) = *(const uint4*)src;
    }
    __syncthreads();

    const int r0 = m0 + wm * 16 + qp;
    const int hid = j0 + wn * 8 + 2 * t4;
    const uint32_t aRowOff = (uint32_t)(wm * 16 + lr) * AST + khalf * 16;

    float c_st[4] = {0.f, 0.f, 0.f, 0.f};

    for (int t = 0; t < TT; ++t) {
        const int rb = t & 1;
        const __nv_bfloat16* hb = g_hsplit[rb];

        float acc[4][4] = {};
        float xv[4][4];

        // stage chunk 0 into A stage 0 (64 rows x 256 k)
        {
            uint4 pf[8];
#pragma unroll
            for (int j = 0; j < 8; j++) {
                int u = tid + j * 256;
                int n = u >> 5, q = u & 31;
                pf[j] = __ldcg((const uint4*)(hb + (size_t)(m0 + n) * 1024 + q * 8));
            }
#pragma unroll
            for (int j = 0; j < 8; j++) {
                int u = tid + j * 256;
                int n = u >> 5, q = u & 31;
                *(uint4*)(smem + SMEM_A0 + n * AST + q * 16) = pf[j];
            }
        }
        __syncthreads();

        for (int s = 0; s < 4; s++) {
            const uint32_t aCur = aB[s & 1];
            uint4 pf[8];
            if (s < 3) {
#pragma unroll
                for (int j = 0; j < 8; j++) {
                    int u = tid + j * 256;
                    int n = u >> 5, q = u & 31;
                    pf[j] = __ldcg((const uint4*)(hb + (size_t)(m0 + n) * 1024
                                                  + (s + 1) * 256 + q * 8));
                }
            } else {
                // prefetch xg[t] into registers under last chunk's compute
#pragma unroll
                for (int g = 0; g < 4; g++) {
                    const float* x0 = g_xg + ((size_t)t * BB + r0) * GG + (g << 9) + hid;
                    const float* x1 = g_xg + ((size_t)t * BB + r0 + 8) * GG + (g << 9) + hid;
                    float2 v0 = __ldcg((const float2*)x0);
                    float2 v1 = __ldcg((const float2*)x1);
                    xv[g][0] = v0.x; xv[g][1] = v0.y;
                    xv[g][2] = v1.x; xv[g][3] = v1.y;
                }
            }

            if (s < 2) {
                // h1 chunk: fused W1 + W2 passes, A fragment reused
                const int kb1 = s * 256;
                const int kb2 = 512 + s * 256;
#pragma unroll 4
                for (int k16 = 0; k16 < 16; k16++) {
                    uint32_t a0, a1, a2, a3;
                    ldsm4(a0, a1, a2, a3, aCur + aRowOff + k16 * 32);
#pragma unroll
                    for (int p = 0; p < 2; p++) {
                        const uint32_t nrow = wn * 32 + p * 16 + lr;
                        uint32_t b0, b1, b2, b3, c0, c1, c2, c3;
                        ldsm4(b0, b1, b2, b3,
                              bB32 + (nrow * BPADE + kb1 + k16 * 16) * 2 + khalf * 16);
                        ldsm4(c0, c1, c2, c3,
                              bB32 + (nrow * BPADE + kb2 + k16 * 16) * 2 + khalf * 16);
                        mma_bf16(acc[2 * p],     a0, a1, a2, a3, b0, b2);
                        mma_bf16(acc[2 * p + 1], a0, a1, a2, a3, b1, b3);
                        mma_bf16(acc[2 * p],     a0, a1, a2, a3, c0, c2);
                        mma_bf16(acc[2 * p + 1], a0, a1, a2, a3, c1, c3);
                    }
                }
            } else {
                // h2 chunk: W1 only
                const int kb1 = (s - 2) * 256;
#pragma unroll 4
                for (int k16 = 0; k16 < 16; k16++) {
                    uint32_t a0, a1, a2, a3;
                    ldsm4(a0, a1, a2, a3, aCur + aRowOff + k16 * 32);
#pragma unroll
                    for (int p = 0; p < 2; p++) {
                        const uint32_t nrow = wn * 32 + p * 16 + lr;
                        uint32_t b0, b1, b2, b3;
                        ldsm4(b0, b1, b2, b3,
                              bB32 + (nrow * BPADE + kb1 + k16 * 16) * 2 + khalf * 16);
                        mma_bf16(acc[2 * p],     a0, a1, a2, a3, b0, b2);
                        mma_bf16(acc[2 * p + 1], a0, a1, a2, a3, b1, b3);
                    }
                }
            }

            if (s < 3) {
                const uint32_t dstOff = SMEM_A0 + ((s + 1) & 1) * ASTAGE;
#pragma unroll
                for (int j = 0; j < 8; j++) {
                    int u = tid + j * 256;
                    int n = u >> 5, q = u & 31;
                    *(uint4*)(smem + dstOff + n * AST + q * 16) = pf[j];
                }
                __syncthreads();
            }
        }

        // pointwise in registers: 4 cells (2 rows x 2 hids)
        float hv[4];
#pragma unroll
        for (int d = 0; d < 4; d++) {
            float gi = acc[0][d] + xv[0][d];
            float gf = acc[1][d] + xv[1][d];
            float gg = acc[2][d] + xv[2][d];
            float go = acc[3][d] + xv[3][d];
            float iv = sigm(gi), fv = sigm(gf), gv = tanh_fast(gg), ov = sigm(go);
            float cc = c_st[d] * fv + iv * gv;
            c_st[d] = cc;
            hv[d] = ov * tanh_fast(cc);
        }

        __nv_bfloat16* hs = g_hsplit[rb ^ 1];
#pragma unroll
        for (int rr = 0; rr < 2; rr++) {
            int row = r0 + rr * 8;
            float h0 = hv[rr * 2], h1 = hv[rr * 2 + 1];
            __nv_bfloat16 p0 = __float2bfloat16(h0);
            __nv_bfloat16 p1 = __float2bfloat16(h1);
            __nv_bfloat16 q0 = __float2bfloat16(h0 - __bfloat162float(p0));
            __nv_bfloat16 q1 = __float2bfloat16(h1 - __bfloat162float(p1));
            *(__nv_bfloat162*)(hs + (size_t)row * 1024 + hid)       = __halves2bfloat162(p0, p1);
            *(__nv_bfloat162*)(hs + (size_t)row * 1024 + 512 + hid) = __halves2bfloat162(q0, q1);
            if (t == TT - 1)
                *(float2*)(g_hfp + (size_t)row * HH + hid) = make_float2(h0, h1);
        }

        grid_bar_fast(t);
    }
}

// ---------------------------------------------------------------------------
__global__ __launch_bounds__(256) void fc_kernel(const float* __restrict__ Wfc,
                                                 const float* __restrict__ bfc,
                                                 float* __restrict__ out) {
    int warp = (blockIdx.x * blockDim.x + threadIdx.x) >> 5;
    int lane = threadIdx.x & 31;
    if (warp >= BB * OO) return;
    int b = warp / OO;
    int o = warp - b * OO;
    const float4* hr = reinterpret_cast<const float4*>(g_hfp + (size_t)b * HH);
    const float4* wr = reinterpret_cast<const float4*>(Wfc + (size_t)o * HH);
    float s = 0.0f;
#pragma unroll
    for (int k = 0; k < 4; k++) {
        float4 h4 = hr[lane + (k << 5)];
        float4 w4 = wr[lane + (k << 5)];
        s += h4.x * w4.x + h4.y * w4.y + h4.z * w4.z + h4.w * w4.w;
    }
#pragma unroll
    for (int off = 16; off; off >>= 1) s += __shfl_xor_sync(0xffffffffu, s, off);
    if (lane == 0) out[warp] = s + bfc[o];
}

// ---------------------------------------------------------------------------
extern "C" void kernel_launch(void* const* d_in, const int* in_sizes, int n_in,
                              void* d_out, int out_size) {
    const float* x   = (const float*)d_in[0];
    const float* Wx  = (const float*)d_in[1];
    const float* bx  = (const float*)d_in[2];
    const float* Wh  = (const float*)d_in[3];
    const float* bh  = (const float*)d_in[4];
    const float* Wfc = (const float*)d_in[5];
    const float* bfc = (const float*)d_in[6];
    float* out = (float*)d_out;

    prep_kernel<<<256, 256>>>(Wh, Wx);
    xsplit_kernel<<<2048, 256>>>(x);

    {
        dim3 grid((TT * BB) / 128, GG / 128);   // (1000, 16)
        cudaFuncSetAttribute(xg_hmma, cudaFuncAttributeMaxDynamicSharedMemorySize, SMEM_XG);
        xg_hmma<<<grid, 256, SMEM_XG>>>(bx, bh);
    }

    cudaFuncSetAttribute(lstm_hmma, cudaFuncAttributeMaxDynamicSharedMemorySize, SMEM_LSTM);
    lstm_hmma<<<NBLK, 256, SMEM_LSTM>>>();

    fc_kernel<<<(BB * OO * 32 + 255) / 256, 256>>>(Wfc, bfc, out);
}

// round 11
// speedup vs baseline: 2.8840x; 1.0770x over previous
#include <cuda_runtime.h>
#include <cuda_bf16.h>
#include <math.h>
#include <cstdint>

#define BB 256
#define TT 500
#define II 256
#define HH 512
#define GG 2048
#define OO 100
#define NBLK 128

typedef unsigned long long ull;

// ------------------------- global scratch (no allocs) -----------------------
__device__ float g_xg[(size_t)TT * BB * GG];            // [T][B][4H]
__device__ __nv_bfloat16 g_xs[(size_t)TT * BB * 512];   // [t*B+b][k]: k<256 x1, >=256 x2
__device__ __nv_bfloat16 g_Wxs[GG * 512];               // [n][k]: k<256 Wx1, >=256 Wx2
__device__ uint4 g_Wfrag[32 * 64 * 4 * 32];             // [bn][kt(0-31 W1,32-63 W2)][nt][lane]
__device__ uint4 g_hfrag[2][64 * 16 * 32];              // [buf][kt(0-31 h1,32-63 h2)][mt][lane]
__device__ float g_hfp[BB * HH];                        // fp32 h (for fc)
__device__ unsigned g_bar_count;

// ------------------------- helpers ------------------------------------------
__device__ __forceinline__ float sigm(float x) { return 1.0f / (1.0f + __expf(-x)); }
__device__ __forceinline__ float tanh_fast(float x) { return 1.0f - 2.0f / (1.0f + __expf(2.0f * x)); }
__device__ __forceinline__ uint32_t smem_u32(const void* p) {
    return (uint32_t)__cvta_generic_to_shared(p);
}
__device__ __forceinline__ void ldsm4(uint32_t& a0, uint32_t& a1, uint32_t& a2, uint32_t& a3,
                                      uint32_t addr) {
    asm volatile("ldmatrix.sync.aligned.m8n8.x4.shared.b16 {%0,%1,%2,%3}, [%4];"
                 : "=r"(a0), "=r"(a1), "=r"(a2), "=r"(a3) : "r"(addr));
}
__device__ __forceinline__ void mma_bf16(float* d, uint32_t a0, uint32_t a1, uint32_t a2,
                                         uint32_t a3, uint32_t b0, uint32_t b1) {
    asm volatile(
        "mma.sync.aligned.m16n8k16.row.col.f32.bf16.bf16.f32 "
        "{%0,%1,%2,%3}, {%4,%5,%6,%7}, {%8,%9}, {%0,%1,%2,%3};"
        : "+f"(d[0]), "+f"(d[1]), "+f"(d[2]), "+f"(d[3])
        : "r"(a0), "r"(a1), "r"(a2), "r"(a3), "r"(b0), "r"(b1));
}
__device__ __forceinline__ uint32_t pack_bf2(float a, float b) {
    __nv_bfloat162 v = __halves2bfloat162(__float2bfloat16(a), __float2bfloat16(b));
    return *reinterpret_cast<uint32_t*>(&v);
}

// ---------------------------------------------------------------------------
// Prep A: split x into g_xs (transposed to [t*B+b] row order)
// ---------------------------------------------------------------------------
__global__ __launch_bounds__(256) void xsplit_kernel(const float* __restrict__ x) {
    const int total = TT * BB * 64;
    const int stride = gridDim.x * blockDim.x;
    for (int idx = blockIdx.x * blockDim.x + threadIdx.x; idx < total; idx += stride) {
        int r = idx >> 6;
        int q = idx & 63;
        int t = r >> 8;
        int b = r & 255;
        float4 v = *(const float4*)(x + ((size_t)b * TT + t) * II + q * 4);
        float r0, r1, r2, r3;
        __nv_bfloat162 h01, h23;
        {
            __nv_bfloat16 p0 = __float2bfloat16(v.x), p1 = __float2bfloat16(v.y);
            __nv_bfloat16 p2 = __float2bfloat16(v.z), p3 = __float2bfloat16(v.w);
            r0 = v.x - __bfloat162float(p0); r1 = v.y - __bfloat162float(p1);
            r2 = v.z - __bfloat162float(p2); r3 = v.w - __bfloat162float(p3);
            h01 = __halves2bfloat162(p0, p1); h23 = __halves2bfloat162(p2, p3);
        }
        __nv_bfloat16* row = g_xs + (size_t)r * 512;
        *(__nv_bfloat162*)(row + q * 4)     = h01;
        *(__nv_bfloat162*)(row + q * 4 + 2) = h23;
        *(__nv_bfloat162*)(row + 256 + q * 4)     = __halves2bfloat162(__float2bfloat16(r0), __float2bfloat16(r1));
        *(__nv_bfloat162*)(row + 256 + q * 4 + 2) = __halves2bfloat162(__float2bfloat16(r2), __float2bfloat16(r3));
    }
}

// ---------------------------------------------------------------------------
// Prep B: Wh -> fragment-major g_Wfrag (W1 hi + W2 residual), Wx -> g_Wxs,
// zero g_hfrag, reset barrier.
// Frag layout (uint32 idx): reg=idx&3, lane=(idx>>2)&31, nt=(idx>>7)&3,
// kt=(idx>>9)&63, bn=idx>>15. Value = bf16x2 of Wh[gcol][kk], [kk+1] where
// n_local = nt*16 + (reg&1)*8 + lane/4; gate=(n>>3)&3; hidl=(n>>5)*8+(n&7);
// gcol = gate*512 + bn*16 + hidl; kk = (kt&31)*16 + ((reg>>1)&1)*8 + 2*(lane&3)
// ---------------------------------------------------------------------------
__global__ __launch_bounds__(256) void prep_kernel(const float* __restrict__ Wh,
                                                   const float* __restrict__ Wx) {
    const int stride = gridDim.x * blockDim.x;
    const int tid0 = blockIdx.x * blockDim.x + threadIdx.x;

    for (int idx = tid0; idx < 32 * 64 * 4 * 32 * 4; idx += stride) {
        int reg = idx & 3, lane = (idx >> 2) & 31, nt = (idx >> 7) & 3;
        int kt = (idx >> 9) & 63, bn = idx >> 15;
        int nl = nt * 16 + (reg & 1) * 8 + (lane >> 2);
        int kk = (kt & 31) * 16 + ((reg >> 1) & 1) * 8 + 2 * (lane & 3);
        int gate = (nl >> 3) & 3;
        int hidl = ((nl >> 5) << 3) + (nl & 7);
        int gcol = (gate << 9) + (bn << 4) + hidl;
        float w0 = Wh[(size_t)gcol * HH + kk];
        float w1 = Wh[(size_t)gcol * HH + kk + 1];
        __nv_bfloat16 h0 = __float2bfloat16(w0), h1 = __float2bfloat16(w1);
        __nv_bfloat162 v;
        if (kt < 32) v = __halves2bfloat162(h0, h1);
        else v = __halves2bfloat162(__float2bfloat16(w0 - __bfloat162float(h0)),
                                    __float2bfloat16(w1 - __bfloat162float(h1)));
        reinterpret_cast<__nv_bfloat162*>(g_Wfrag)[idx] = v;
    }

    for (int idx = tid0; idx < GG * II; idx += stride) {
        int n = idx >> 8, k = idx & 255;
        float w = Wx[idx];
        __nv_bfloat16 w1 = __float2bfloat16(w);
        g_Wxs[(size_t)n * 512 + k] = w1;
        g_Wxs[(size_t)n * 512 + 256 + k] = __float2bfloat16(w - __bfloat162float(w1));
    }

    for (int idx = tid0; idx < 2 * 64 * 16 * 32; idx += stride)
        reinterpret_cast<uint4*>(g_hfrag)[idx] = make_uint4(0, 0, 0, 0);

    if (tid0 == 0) g_bar_count = 0;
}

// ---------------------------------------------------------------------------
// Kernel 1: xg = x @ Wx^T + bx + bh via HMMA 3-term split (round-9, PASS)
// ---------------------------------------------------------------------------
#define XPAD 72
#define XCHUNK (128 * XPAD * 2)
#define SMEM_XG (4 * XCHUNK)

__global__ __launch_bounds__(256, 1) void xg_hmma(const float* __restrict__ bx,
                                                  const float* __restrict__ bh) {
    extern __shared__ char smem[];
    const int tid = threadIdx.x;
    const int wid = tid >> 5;
    const int lane = tid & 31;
    const int wm = wid & 3;
    const int wn = wid >> 2;
    const int lr = lane & 15;
    const int khalf = lane >> 4;
    const int qp = lane >> 2;
    const int t4 = lane & 3;

    const size_t mBase = (size_t)blockIdx.x * 128;
    const int nBase = blockIdx.y * 128;

    const uint32_t aS[2] = { smem_u32(smem), smem_u32(smem) + XCHUNK };
    const uint32_t bS[2] = { aS[0] + 2 * XCHUNK, aS[0] + 3 * XCHUNK };

    float2 biasv[8];
#pragma unroll
    for (int nb = 0; nb < 8; nb++) {
        int col = nBase + wn * 64 + nb * 8 + 2 * t4;
        biasv[nb] = make_float2(bx[col] + bh[col], bx[col + 1] + bh[col + 1]);
    }

    float acc[2][8][4] = {};
    uint4 pfA[4], pfB[4];

    auto aCol = [](int c) { return ((c >> 2) == 1 ? 256 : 0) + (c & 3) * 64; };
    auto bCol = [](int c) { return ((c >> 2) == 2 ? 256 : 0) + (c & 3) * 64; };

#pragma unroll
    for (int j = 0; j < 4; j++) {
        int u = tid + j * 256;
        int n = u >> 3, q = u & 7;
        pfA[j] = *(const uint4*)(g_xs + (mBase + n) * 512 + aCol(0) + q * 8);
        pfB[j] = *(const uint4*)(g_Wxs + (size_t)(nBase + n) * 512 + bCol(0) + q * 8);
    }
#pragma unroll
    for (int j = 0; j < 4; j++) {
        int u = tid + j * 256;
        int n = u >> 3, q = u & 7;
        *(uint4*)(smem + (size_t)n * (XPAD * 2) + q * 16) = pfA[j];
        *(uint4*)(smem + 2 * XCHUNK + (size_t)n * (XPAD * 2) + q * 16) = pfB[j];
    }
    __syncthreads();

    for (int c = 0; c < 12; c++) {
        const int st = c & 1;
        if (c < 11) {
#pragma unroll
            for (int j = 0; j < 4; j++) {
                int u = tid + j * 256;
                int n = u >> 3, q = u & 7;
                pfA[j] = *(const uint4*)(g_xs + (mBase + n) * 512 + aCol(c + 1) + q * 8);
                pfB[j] = *(const uint4*)(g_Wxs + (size_t)(nBase + n) * 512 + bCol(c + 1) + q * 8);
            }
        }
#pragma unroll
        for (int k16 = 0; k16 < 4; k16++) {
            uint32_t a[2][4];
#pragma unroll
            for (int mi = 0; mi < 2; mi++) {
                uint32_t addr = aS[st] + (uint32_t)(wm * 32 + mi * 16 + lr) * (XPAD * 2)
                                + k16 * 32 + khalf * 16;
                ldsm4(a[mi][0], a[mi][1], a[mi][2], a[mi][3], addr);
            }
#pragma unroll
            for (int p = 0; p < 4; p++) {
                uint32_t b0, b1, b2, b3;
                uint32_t addr = bS[st] + (uint32_t)(wn * 64 + p * 16 + lr) * (XPAD * 2)
                                + k16 * 32 + khalf * 16;
                ldsm4(b0, b1, b2, b3, addr);
#pragma unroll
                for (int mi = 0; mi < 2; mi++) {
                    mma_bf16(acc[mi][2 * p],     a[mi][0], a[mi][1], a[mi][2], a[mi][3], b0, b2);
                    mma_bf16(acc[mi][2 * p + 1], a[mi][0], a[mi][1], a[mi][2], a[mi][3], b1, b3);
                }
            }
        }
        if (c < 11) {
            const int ns = (c + 1) & 1;
#pragma unroll
            for (int j = 0; j < 4; j++) {
                int u = tid + j * 256;
                int n = u >> 3, q = u & 7;
                *(uint4*)(smem + (size_t)ns * XCHUNK + (size_t)n * (XPAD * 2) + q * 16) = pfA[j];
                *(uint4*)(smem + 2 * XCHUNK + (size_t)ns * XCHUNK + (size_t)n * (XPAD * 2) + q * 16) = pfB[j];
            }
            __syncthreads();
        }
    }

#pragma unroll
    for (int mi = 0; mi < 2; mi++) {
#pragma unroll
        for (int rr = 0; rr < 2; rr++) {
            size_t row = mBase + wm * 32 + mi * 16 + qp + rr * 8;
            float* orow = g_xg + row * GG + nBase + wn * 64;
#pragma unroll
            for (int nb = 0; nb < 8; nb++) {
                float2 o = make_float2(acc[mi][nb][2 * rr] + biasv[nb].x,
                                       acc[mi][nb][2 * rr + 1] + biasv[nb].y);
                *(float2*)(orow + nb * 8 + 2 * t4) = o;
            }
        }
    }
}

// ---------------------------------------------------------------------------
// Grid barrier: RED arrive, all blocks poll the monotonic counter.
// ---------------------------------------------------------------------------
__device__ __forceinline__ void grid_bar_fast(unsigned ep) {
    __syncthreads();
    if (threadIdx.x == 0) {
        __threadfence();
        atomicAdd(&g_bar_count, 1u);     // result unused -> RED
        const unsigned target = (ep + 1) * NBLK;
        while (*(volatile unsigned*)&g_bar_count < target) {}
        __threadfence();
    }
    __syncthreads();
}

// ---------------------------------------------------------------------------
// Kernel 2: persistent HMMA LSTM recurrence v3 — fragment-direct, zero smem.
// 128 blocks x 256 threads; block (bm, bn) = 64 batch rows x 64 gate-cols.
// 8 warps: wm 0..3 (16-row tiles), wn 0..1 (32-col halves).
// A fragments ldg'ed directly from g_hfrag (written in frag layout by the
// previous step's epilogue). B fragments ldg'ed from g_Wfrag (L1-resident,
// 128KB/block, smem=0 so full 228KB L1; A/xg use .cg to bypass L1).
// Per k16 tile: 2 A ldg + 4 B ldg + 12 mma (h1W1 + h1W2 + h2W1 fused).
// No ldsm, no smem, no per-chunk __syncthreads.
// ---------------------------------------------------------------------------
__global__ __launch_bounds__(256, 1) void lstm_hmma() {
    const int tid = threadIdx.x;
    const int lane = tid & 31;
    const int wid = tid >> 5;
    const int wm = wid & 3;
    const int wn = wid >> 2;
    const int qp = lane >> 2;
    const int t4 = lane & 3;

    const int bm = blockIdx.x >> 5;
    const int bn = blockIdx.x & 31;
    const int m0 = bm << 6;
    const int j0 = bn << 4;
    const int mt = bm * 4 + wm;
    const int r0 = m0 + wm * 16 + qp;
    const int hid = j0 + wn * 8 + 2 * t4;

    // B frag base: index ((bn*64 + kt)*4 + 2wn)*32 + lane; kt stride = 128 uint4
    const uint4* WfBase = g_Wfrag + (((size_t)bn * 64) * 4 + 2 * wn) * 32 + lane;

    float c_st[4] = {0.f, 0.f, 0.f, 0.f};

    for (int t = 0; t < TT; ++t) {
        const int rb = t & 1;
        const uint4* Af = g_hfrag[rb] + (size_t)mt * 32 + lane;  // + kt*512

        // xg prefetch (DRAM, consumed at epilogue)
        float xv[4][4];
#pragma unroll
        for (int g = 0; g < 4; g++) {
            float2 v0 = __ldcg((const float2*)(g_xg + ((size_t)t * BB + r0) * GG + (g << 9) + hid));
            float2 v1 = __ldcg((const float2*)(g_xg + ((size_t)t * BB + r0 + 8) * GG + (g << 9) + hid));
            xv[g][0] = v0.x; xv[g][1] = v0.y; xv[g][2] = v1.x; xv[g][3] = v1.y;
        }

        // A prefetch queues (8 tiles deep, h1 + h2)
        uint4 a1q[8], a2q[8];
#pragma unroll
        for (int j = 0; j < 8; j++) {
            a1q[j] = __ldcg(Af + (size_t)j * 512);
            a2q[j] = __ldcg(Af + (size_t)(j + 32) * 512);
        }

        float acc[4][4] = {};

#pragma unroll 8
        for (int kt = 0; kt < 32; kt++) {
            uint4 A1 = a1q[kt & 7], A2 = a2q[kt & 7];
            if (kt < 24) {
                a1q[kt & 7] = __ldcg(Af + (size_t)(kt + 8) * 512);
                a2q[kt & 7] = __ldcg(Af + (size_t)(kt + 40) * 512);
            }
            const uint4* wp = WfBase + (size_t)kt * 128;
            uint4 B1a = wp[0], B1b = wp[32];
            uint4 B2a = wp[32 * 128], B2b = wp[32 * 128 + 32];

            mma_bf16(acc[0], A1.x, A1.y, A1.z, A1.w, B1a.x, B1a.z);
            mma_bf16(acc[1], A1.x, A1.y, A1.z, A1.w, B1a.y, B1a.w);
            mma_bf16(acc[2], A1.x, A1.y, A1.z, A1.w, B1b.x, B1b.z);
            mma_bf16(acc[3], A1.x, A1.y, A1.z, A1.w, B1b.y, B1b.w);
            mma_bf16(acc[0], A1.x, A1.y, A1.z, A1.w, B2a.x, B2a.z);
            mma_bf16(acc[1], A1.x, A1.y, A1.z, A1.w, B2a.y, B2a.w);
            mma_bf16(acc[2], A1.x, A1.y, A1.z, A1.w, B2b.x, B2b.z);
            mma_bf16(acc[3], A1.x, A1.y, A1.z, A1.w, B2b.y, B2b.w);
            mma_bf16(acc[0], A2.x, A2.y, A2.z, A2.w, B1a.x, B1a.z);
            mma_bf16(acc[1], A2.x, A2.y, A2.z, A2.w, B1a.y, B1a.w);
            mma_bf16(acc[2], A2.x, A2.y, A2.z, A2.w, B1b.x, B1b.z);
            mma_bf16(acc[3], A2.x, A2.y, A2.z, A2.w, B1b.y, B1b.w);
        }

        // pointwise in registers
        float hv[4];
#pragma unroll
        for (int d = 0; d < 4; d++) {
            float gi = acc[0][d] + xv[0][d];
            float gf = acc[1][d] + xv[1][d];
            float gg = acc[2][d] + xv[2][d];
            float go = acc[3][d] + xv[3][d];
            float iv = sigm(gi), fv = sigm(gf), gv = tanh_fast(gg), ov = sigm(go);
            float cc = c_st[d] * fv + iv * gv;
            c_st[d] = cc;
            hv[d] = ov * tanh_fast(cc);
        }

        // store h directly in A-fragment layout (hi + residual)
        uint32_t P01 = pack_bf2(hv[0], hv[1]);
        uint32_t P23 = pack_bf2(hv[2], hv[3]);
        float q0 = hv[0] - __bfloat162float(__float2bfloat16(hv[0]));
        float q1 = hv[1] - __bfloat162float(__float2bfloat16(hv[1]));
        float q2 = hv[2] - __bfloat162float(__float2bfloat16(hv[2]));
        float q3 = hv[3] - __bfloat162float(__float2bfloat16(hv[3]));
        uint32_t Q01 = pack_bf2(q0, q1);
        uint32_t Q23 = pack_bf2(q2, q3);

        uint4* hb = g_hfrag[rb ^ 1];
        char* d1 = (char*)(hb + ((size_t)bn * 16 + mt) * 32 + lane) + wn * 8;
        *(uint2*)d1 = make_uint2(P01, P23);
        char* d2 = (char*)(hb + ((size_t)(bn + 32) * 16 + mt) * 32 + lane) + wn * 8;
        *(uint2*)d2 = make_uint2(Q01, Q23);

        if (t == TT - 1) {
            *(float2*)(g_hfp + (size_t)r0 * HH + hid)       = make_float2(hv[0], hv[1]);
            *(float2*)(g_hfp + (size_t)(r0 + 8) * HH + hid) = make_float2(hv[2], hv[3]);
        }

        grid_bar_fast(t);
    }
}

// ---------------------------------------------------------------------------
__global__ __launch_bounds__(256) void fc_kernel(const float* __restrict__ Wfc,
                                                 const float* __restrict__ bfc,
                                                 float* __restrict__ out) {
    int warp = (blockIdx.x * blockDim.x + threadIdx.x) >> 5;
    int lane = threadIdx.x & 31;
    if (warp >= BB * OO) return;
    int b = warp / OO;
    int o = warp - b * OO;
    const float4* hr = reinterpret_cast<const float4*>(g_hfp + (size_t)b * HH);
    const float4* wr = reinterpret_cast<const float4*>(Wfc + (size_t)o * HH);
    float s = 0.0f;
#pragma unroll
    for (int k = 0; k < 4; k++) {
        float4 h4 = hr[lane + (k << 5)];
        float4 w4 = wr[lane + (k << 5)];
        s += h4.x * w4.x + h4.y * w4.y + h4.z * w4.z + h4.w * w4.w;
    }
#pragma unroll
    for (int off = 16; off; off >>= 1) s += __shfl_xor_sync(0xffffffffu, s, off);
    if (lane == 0) out[warp] = s + bfc[o];
}

// ---------------------------------------------------------------------------
extern "C" void kernel_launch(void* const* d_in, const int* in_sizes, int n_in,
                              void* d_out, int out_size) {
    const float* x   = (const float*)d_in[0];
    const float* Wx  = (const float*)d_in[1];
    const float* bx  = (const float*)d_in[2];
    const float* Wh  = (const float*)d_in[3];
    const float* bh  = (const float*)d_in[4];
    const float* Wfc = (const float*)d_in[5];
    const float* bfc = (const float*)d_in[6];
    float* out = (float*)d_out;

    prep_kernel<<<2048, 256>>>(Wh, Wx);
    xsplit_kernel<<<2048, 256>>>(x);

    {
        dim3 grid((TT * BB) / 128, GG / 128);   // (1000, 16)
        cudaFuncSetAttribute(xg_hmma, cudaFuncAttributeMaxDynamicSharedMemorySize, SMEM_XG);
        xg_hmma<<<grid, 256, SMEM_XG>>>(bx, bh);
    }

    lstm_hmma<<<NBLK, 256>>>();

    fc_kernel<<<(BB * OO * 32 + 255) / 256, 256>>>(Wfc, bfc, out);
}

// round 12
// speedup vs baseline: 3.3234x; 1.1524x over previous
#include <cuda_runtime.h>
#include <cuda_bf16.h>
#include <math.h>
#include <cstdint>

#define BB 256
#define TT 500
#define II 256
#define HH 512
#define GG 2048
#define OO 100
#define NBLK 128

typedef unsigned long long ull;

// ------------------------- global scratch (no allocs) -----------------------
__device__ float g_xg[(size_t)TT * BB * GG];            // [T][B][4H]
__device__ __nv_bfloat16 g_xs[(size_t)TT * BB * 512];   // [t*B+b][k]: k<256 x1, >=256 x2
__device__ __nv_bfloat16 g_Wxs[GG * 512];               // [n][k]: k<256 Wx1, >=256 Wx2
__device__ uint4 g_Wfrag[32 * 64 * 4 * 32];             // [bn][kt(0-31 W1,32-63 W2)][nt][lane]
__device__ uint4 g_hfrag[2][64 * 16 * 32];              // [buf][kt(0-31 h1,32-63 h2)][mt][lane]
__device__ float g_hfp[BB * HH];                        // fp32 h (for fc)
__device__ unsigned g_barc[4 * 32];                     // 4 group counters, 128B apart

// ------------------------- helpers ------------------------------------------
__device__ __forceinline__ float sigm(float x) { return 1.0f / (1.0f + __expf(-x)); }
__device__ __forceinline__ float tanh_fast(float x) { return 1.0f - 2.0f / (1.0f + __expf(2.0f * x)); }
__device__ __forceinline__ uint32_t smem_u32(const void* p) {
    return (uint32_t)__cvta_generic_to_shared(p);
}
__device__ __forceinline__ void ldsm4(uint32_t& a0, uint32_t& a1, uint32_t& a2, uint32_t& a3,
                                      uint32_t addr) {
    asm volatile("ldmatrix.sync.aligned.m8n8.x4.shared.b16 {%0,%1,%2,%3}, [%4];"
                 : "=r"(a0), "=r"(a1), "=r"(a2), "=r"(a3) : "r"(addr));
}
__device__ __forceinline__ void mma_bf16(float* d, uint32_t a0, uint32_t a1, uint32_t a2,
                                         uint32_t a3, uint32_t b0, uint32_t b1) {
    asm volatile(
        "mma.sync.aligned.m16n8k16.row.col.f32.bf16.bf16.f32 "
        "{%0,%1,%2,%3}, {%4,%5,%6,%7}, {%8,%9}, {%0,%1,%2,%3};"
        : "+f"(d[0]), "+f"(d[1]), "+f"(d[2]), "+f"(d[3])
        : "r"(a0), "r"(a1), "r"(a2), "r"(a3), "r"(b0), "r"(b1));
}
__device__ __forceinline__ uint32_t pack_bf2(float a, float b) {
    __nv_bfloat162 v = __halves2bfloat162(__float2bfloat16(a), __float2bfloat16(b));
    return *reinterpret_cast<uint32_t*>(&v);
}

// ---------------------------------------------------------------------------
// Prep A: split x into g_xs (transposed to [t*B+b] row order)
// ---------------------------------------------------------------------------
__global__ __launch_bounds__(256) void xsplit_kernel(const float* __restrict__ x) {
    const int total = TT * BB * 64;
    const int stride = gridDim.x * blockDim.x;
    for (int idx = blockIdx.x * blockDim.x + threadIdx.x; idx < total; idx += stride) {
        int r = idx >> 6;
        int q = idx & 63;
        int t = r >> 8;
        int b = r & 255;
        float4 v = *(const float4*)(x + ((size_t)b * TT + t) * II + q * 4);
        float r0, r1, r2, r3;
        __nv_bfloat162 h01, h23;
        {
            __nv_bfloat16 p0 = __float2bfloat16(v.x), p1 = __float2bfloat16(v.y);
            __nv_bfloat16 p2 = __float2bfloat16(v.z), p3 = __float2bfloat16(v.w);
            r0 = v.x - __bfloat162float(p0); r1 = v.y - __bfloat162float(p1);
            r2 = v.z - __bfloat162float(p2); r3 = v.w - __bfloat162float(p3);
            h01 = __halves2bfloat162(p0, p1); h23 = __halves2bfloat162(p2, p3);
        }
        __nv_bfloat16* row = g_xs + (size_t)r * 512;
        *(__nv_bfloat162*)(row + q * 4)     = h01;
        *(__nv_bfloat162*)(row + q * 4 + 2) = h23;
        *(__nv_bfloat162*)(row + 256 + q * 4)     = __halves2bfloat162(__float2bfloat16(r0), __float2bfloat16(r1));
        *(__nv_bfloat162*)(row + 256 + q * 4 + 2) = __halves2bfloat162(__float2bfloat16(r2), __float2bfloat16(r3));
    }
}

// ---------------------------------------------------------------------------
// Prep B: Wh -> fragment-major g_Wfrag (unchanged layout, validated R8-R11),
// Wx -> g_Wxs, zero g_hfrag, reset group barriers.
// ---------------------------------------------------------------------------
__global__ __launch_bounds__(256) void prep_kernel(const float* __restrict__ Wh,
                                                   const float* __restrict__ Wx) {
    const int stride = gridDim.x * blockDim.x;
    const int tid0 = blockIdx.x * blockDim.x + threadIdx.x;

    for (int idx = tid0; idx < 32 * 64 * 4 * 32 * 4; idx += stride) {
        int reg = idx & 3, lane = (idx >> 2) & 31, nt = (idx >> 7) & 3;
        int kt = (idx >> 9) & 63, bn = idx >> 15;
        int nl = nt * 16 + (reg & 1) * 8 + (lane >> 2);
        int kk = (kt & 31) * 16 + ((reg >> 1) & 1) * 8 + 2 * (lane & 3);
        int gate = (nl >> 3) & 3;
        int hidl = ((nl >> 5) << 3) + (nl & 7);
        int gcol = (gate << 9) + (bn << 4) + hidl;
        float w0 = Wh[(size_t)gcol * HH + kk];
        float w1 = Wh[(size_t)gcol * HH + kk + 1];
        __nv_bfloat16 h0 = __float2bfloat16(w0), h1 = __float2bfloat16(w1);
        __nv_bfloat162 v;
        if (kt < 32) v = __halves2bfloat162(h0, h1);
        else v = __halves2bfloat162(__float2bfloat16(w0 - __bfloat162float(h0)),
                                    __float2bfloat16(w1 - __bfloat162float(h1)));
        reinterpret_cast<__nv_bfloat162*>(g_Wfrag)[idx] = v;
    }

    for (int idx = tid0; idx < GG * II; idx += stride) {
        int n = idx >> 8, k = idx & 255;
        float w = Wx[idx];
        __nv_bfloat16 w1 = __float2bfloat16(w);
        g_Wxs[(size_t)n * 512 + k] = w1;
        g_Wxs[(size_t)n * 512 + 256 + k] = __float2bfloat16(w - __bfloat162float(w1));
    }

    for (int idx = tid0; idx < 2 * 64 * 16 * 32; idx += stride)
        reinterpret_cast<uint4*>(g_hfrag)[idx] = make_uint4(0, 0, 0, 0);

    if (tid0 < 4 * 32) g_barc[tid0] = 0;
}

// ---------------------------------------------------------------------------
// Kernel 1: xg = x @ Wx^T + bx + bh via HMMA 3-term split (round-9, PASS)
// ---------------------------------------------------------------------------
#define XPAD 72
#define XCHUNK (128 * XPAD * 2)
#define SMEM_XG (4 * XCHUNK)

__global__ __launch_bounds__(256, 1) void xg_hmma(const float* __restrict__ bx,
                                                  const float* __restrict__ bh) {
    extern __shared__ char smem[];
    const int tid = threadIdx.x;
    const int wid = tid >> 5;
    const int lane = tid & 31;
    const int wm = wid & 3;
    const int wn = wid >> 2;
    const int lr = lane & 15;
    const int khalf = lane >> 4;
    const int qp = lane >> 2;
    const int t4 = lane & 3;

    const size_t mBase = (size_t)blockIdx.x * 128;
    const int nBase = blockIdx.y * 128;

    const uint32_t aS[2] = { smem_u32(smem), smem_u32(smem) + XCHUNK };
    const uint32_t bS[2] = { aS[0] + 2 * XCHUNK, aS[0] + 3 * XCHUNK };

    float2 biasv[8];
#pragma unroll
    for (int nb = 0; nb < 8; nb++) {
        int col = nBase + wn * 64 + nb * 8 + 2 * t4;
        biasv[nb] = make_float2(bx[col] + bh[col], bx[col + 1] + bh[col + 1]);
    }

    float acc[2][8][4] = {};
    uint4 pfA[4], pfB[4];

    auto aCol = [](int c) { return ((c >> 2) == 1 ? 256 : 0) + (c & 3) * 64; };
    auto bCol = [](int c) { return ((c >> 2) == 2 ? 256 : 0) + (c & 3) * 64; };

#pragma unroll
    for (int j = 0; j < 4; j++) {
        int u = tid + j * 256;
        int n = u >> 3, q = u & 7;
        pfA[j] = *(const uint4*)(g_xs + (mBase + n) * 512 + aCol(0) + q * 8);
        pfB[j] = *(const uint4*)(g_Wxs + (size_t)(nBase + n) * 512 + bCol(0) + q * 8);
    }
#pragma unroll
    for (int j = 0; j < 4; j++) {
        int u = tid + j * 256;
        int n = u >> 3, q = u & 7;
        *(uint4*)(smem + (size_t)n * (XPAD * 2) + q * 16) = pfA[j];
        *(uint4*)(smem + 2 * XCHUNK + (size_t)n * (XPAD * 2) + q * 16) = pfB[j];
    }
    __syncthreads();

    for (int c = 0; c < 12; c++) {
        const int st = c & 1;
        if (c < 11) {
#pragma unroll
            for (int j = 0; j < 4; j++) {
                int u = tid + j * 256;
                int n = u >> 3, q = u & 7;
                pfA[j] = *(const uint4*)(g_xs + (mBase + n) * 512 + aCol(c + 1) + q * 8);
                pfB[j] = *(const uint4*)(g_Wxs + (size_t)(nBase + n) * 512 + bCol(c + 1) + q * 8);
            }
        }
#pragma unroll
        for (int k16 = 0; k16 < 4; k16++) {
            uint32_t a[2][4];
#pragma unroll
            for (int mi = 0; mi < 2; mi++) {
                uint32_t addr = aS[st] + (uint32_t)(wm * 32 + mi * 16 + lr) * (XPAD * 2)
                                + k16 * 32 + khalf * 16;
                ldsm4(a[mi][0], a[mi][1], a[mi][2], a[mi][3], addr);
            }
#pragma unroll
            for (int p = 0; p < 4; p++) {
                uint32_t b0, b1, b2, b3;
                uint32_t addr = bS[st] + (uint32_t)(wn * 64 + p * 16 + lr) * (XPAD * 2)
                                + k16 * 32 + khalf * 16;
                ldsm4(b0, b1, b2, b3, addr);
#pragma unroll
                for (int mi = 0; mi < 2; mi++) {
                    mma_bf16(acc[mi][2 * p],     a[mi][0], a[mi][1], a[mi][2], a[mi][3], b0, b2);
                    mma_bf16(acc[mi][2 * p + 1], a[mi][0], a[mi][1], a[mi][2], a[mi][3], b1, b3);
                }
            }
        }
        if (c < 11) {
            const int ns = (c + 1) & 1;
#pragma unroll
            for (int j = 0; j < 4; j++) {
                int u = tid + j * 256;
                int n = u >> 3, q = u & 7;
                *(uint4*)(smem + (size_t)ns * XCHUNK + (size_t)n * (XPAD * 2) + q * 16) = pfA[j];
                *(uint4*)(smem + 2 * XCHUNK + (size_t)ns * XCHUNK + (size_t)n * (XPAD * 2) + q * 16) = pfB[j];
            }
            __syncthreads();
        }
    }

#pragma unroll
    for (int mi = 0; mi < 2; mi++) {
#pragma unroll
        for (int rr = 0; rr < 2; rr++) {
            size_t row = mBase + wm * 32 + mi * 16 + qp + rr * 8;
            float* orow = g_xg + row * GG + nBase + wn * 64;
#pragma unroll
            for (int nb = 0; nb < 8; nb++) {
                float2 o = make_float2(acc[mi][nb][2 * rr] + biasv[nb].x,
                                       acc[mi][nb][2 * rr + 1] + biasv[nb].y);
                *(float2*)(orow + nb * 8 + 2 * t4) = o;
            }
        }
    }
}

// ---------------------------------------------------------------------------
// Kernel 2: persistent HMMA LSTM recurrence v4 — 512 threads, 16 warps.
// Block (bm, bn): 64 batch rows x 64 gate-cols. Warp (wm 0..3, wn 0..3):
// M16 x N16 tile (nt = wn in g_Wfrag). Per kt: 2 A ldg + 2 B ldg + 6 mma.
// Gates tile goes through 18KB smem; pointwise threads own (row, hid 2v..2v+1)
// and write h1/h2 bf16x2 words directly into the next A-fragment layout.
// Group barrier per bm (32 blocks): h coupling is within-bm only.
// ---------------------------------------------------------------------------
#define SGROW 18   // floats per row in gates smem (16 + 2 pad)

__global__ __launch_bounds__(512, 1) void lstm_hmma() {
    __shared__ float sg[4 * 64 * SGROW];   // [gate][row 64][hid 16 (+2)]

    const int tid = threadIdx.x;
    const int lane = tid & 31;
    const int wid = tid >> 5;
    const int wm = wid & 3;
    const int wn = wid >> 2;
    const int qp = lane >> 2;
    const int t4 = lane & 3;

    const int bm = blockIdx.x >> 5;
    const int bn = blockIdx.x & 31;
    const int m0 = bm << 6;
    const int j0 = bn << 4;
    const int mt = bm * 4 + wm;

    // B frag base for this warp's nt = wn
    const uint4* WfBase = g_Wfrag + (((size_t)bn * 64) * 4 + wn) * 32 + lane;

    // pointwise mapping: row_l = tid>>3 (0..63), v = tid&7 -> hid pair 2v,2v+1
    const int prow = tid >> 3;
    const int pv = tid & 7;
    const int grow = m0 + prow;
    const int ghid = j0 + 2 * pv;
    // h-frag store coords for (prow, 2v..2v+1)
    const int pmt = bm * 4 + (prow >> 4);
    const int r16 = prow & 15;
    const int comp = (r16 >> 3) + 2 * (pv >> 2);
    const int plane = (r16 & 7) * 4 + (pv & 3);

    // group barrier
    unsigned* barp = &g_barc[bm * 32];

    float c0 = 0.f, c1 = 0.f;

    for (int t = 0; t < TT; ++t) {
        const int rb = t & 1;
        const uint4* Af = g_hfrag[rb] + (size_t)mt * 32 + lane;  // + kt*512

        // xg prefetch for pointwise cells (4 gates x hid pair), DRAM-latency
        // hidden under the MMA loop
        float2 xv[4];
#pragma unroll
        for (int g = 0; g < 4; g++)
            xv[g] = __ldcg((const float2*)(g_xg + ((size_t)t * BB + grow) * GG + (g << 9) + ghid));

        // A prefetch queues (4 deep, h1 + h2)
        uint4 a1q[4], a2q[4];
#pragma unroll
        for (int j = 0; j < 4; j++) {
            a1q[j] = __ldcg(Af + (size_t)j * 512);
            a2q[j] = __ldcg(Af + (size_t)(j + 32) * 512);
        }

        float acc[2][4] = {};

#pragma unroll
        for (int kt = 0; kt < 32; kt++) {
            uint4 A1 = a1q[kt & 3], A2 = a2q[kt & 3];
            if (kt < 28) {
                a1q[kt & 3] = __ldcg(Af + (size_t)(kt + 4) * 512);
                a2q[kt & 3] = __ldcg(Af + (size_t)(kt + 36) * 512);
            }
            const uint4* wp = WfBase + (size_t)kt * 128;
            uint4 B1 = wp[0];
            uint4 B2 = wp[32 * 128];

            mma_bf16(acc[0], A1.x, A1.y, A1.z, A1.w, B1.x, B1.z);
            mma_bf16(acc[1], A1.x, A1.y, A1.z, A1.w, B1.y, B1.w);
            mma_bf16(acc[0], A1.x, A1.y, A1.z, A1.w, B2.x, B2.z);
            mma_bf16(acc[1], A1.x, A1.y, A1.z, A1.w, B2.y, B2.w);
            mma_bf16(acc[0], A2.x, A2.y, A2.z, A2.w, B1.x, B1.z);
            mma_bf16(acc[1], A2.x, A2.y, A2.z, A2.w, B1.y, B1.w);
        }

        // stage gates to smem: acc[p][d]: gate=(2wn+p)&3, row=wm*16+qp+8*(d>>1),
        // hid=(wn>>1)*8 + 2t4 + (d&1)
#pragma unroll
        for (int p = 0; p < 2; p++) {
            int gate = (2 * wn + p) & 3;
            int hidb = ((wn >> 1) << 3) + 2 * t4;
            float* s0 = &sg[(gate * 64 + wm * 16 + qp) * SGROW + hidb];
            *(float2*)s0 = make_float2(acc[p][0], acc[p][1]);
            float* s1 = &sg[(gate * 64 + wm * 16 + qp + 8) * SGROW + hidb];
            *(float2*)s1 = make_float2(acc[p][2], acc[p][3]);
        }
        __syncthreads();

        // pointwise: 2 cells (grow, ghid), (grow, ghid+1)
        float hv0, hv1;
        {
            float2 gi = *(const float2*)&sg[(0 * 64 + prow) * SGROW + 2 * pv];
            float2 gf = *(const float2*)&sg[(1 * 64 + prow) * SGROW + 2 * pv];
            float2 gg = *(const float2*)&sg[(2 * 64 + prow) * SGROW + 2 * pv];
            float2 go = *(const float2*)&sg[(3 * 64 + prow) * SGROW + 2 * pv];
            float i0 = sigm(gi.x + xv[0].x), i1 = sigm(gi.y + xv[0].y);
            float f0 = sigm(gf.x + xv[1].x), f1 = sigm(gf.y + xv[1].y);
            float g0 = tanh_fast(gg.x + xv[2].x), g1 = tanh_fast(gg.y + xv[2].y);
            float o0 = sigm(go.x + xv[3].x), o1 = sigm(go.y + xv[3].y);
            c0 = c0 * f0 + i0 * g0;
            c1 = c1 * f1 + i1 * g1;
            hv0 = o0 * tanh_fast(c0);
            hv1 = o1 * tanh_fast(c1);
        }

        // store h in A-fragment layout: hi word + residual word
        uint32_t P = pack_bf2(hv0, hv1);
        float q0 = hv0 - __bfloat162float(__float2bfloat16(hv0));
        float q1 = hv1 - __bfloat162float(__float2bfloat16(hv1));
        uint32_t Q = pack_bf2(q0, q1);

        uint4* hb = g_hfrag[rb ^ 1];
        uint32_t* d1 = (uint32_t*)(hb + ((size_t)bn * 16 + pmt) * 32 + plane) + comp;
        *d1 = P;
        uint32_t* d2 = (uint32_t*)(hb + ((size_t)(bn + 32) * 16 + pmt) * 32 + plane) + comp;
        *d2 = Q;

        if (t == TT - 1)
            *(float2*)(g_hfp + (size_t)grow * HH + ghid) = make_float2(hv0, hv1);

        // group barrier (RED arrive + poll monotonic counter), also covers the
        // smem gates tile reuse (syncthreads below)
        __syncthreads();
        if (tid == 0) {
            __threadfence();
            atomicAdd(barp, 1u);
            const unsigned target = (t + 1) * 32;
            while (*(volatile unsigned*)barp < target) {}
            __threadfence();
        }
        __syncthreads();
    }
}

// ---------------------------------------------------------------------------
__global__ __launch_bounds__(256) void fc_kernel(const float* __restrict__ Wfc,
                                                 const float* __restrict__ bfc,
                                                 float* __restrict__ out) {
    int warp = (blockIdx.x * blockDim.x + threadIdx.x) >> 5;
    int lane = threadIdx.x & 31;
    if (warp >= BB * OO) return;
    int b = warp / OO;
    int o = warp - b * OO;
    const float4* hr = reinterpret_cast<const float4*>(g_hfp + (size_t)b * HH);
    const float4* wr = reinterpret_cast<const float4*>(Wfc + (size_t)o * HH);
    float s = 0.0f;
#pragma unroll
    for (int k = 0; k < 4; k++) {
        float4 h4 = hr[lane + (k << 5)];
        float4 w4 = wr[lane + (k << 5)];
        s += h4.x * w4.x + h4.y * w4.y + h4.z * w4.z + h4.w * w4.w;
    }
#pragma unroll
    for (int off = 16; off; off >>= 1) s += __shfl_xor_sync(0xffffffffu, s, off);
    if (lane == 0) out[warp] = s + bfc[o];
}

// ---------------------------------------------------------------------------
extern "C" void kernel_launch(void* const* d_in, const int* in_sizes, int n_in,
                              void* d_out, int out_size) {
    const float* x   = (const float*)d_in[0];
    const float* Wx  = (const float*)d_in[1];
    const float* bx  = (const float*)d_in[2];
    const float* Wh  = (const float*)d_in[3];
    const float* bh  = (const float*)d_in[4];
    const float* Wfc = (const float*)d_in[5];
    const float* bfc = (const float*)d_in[6];
    float* out = (float*)d_out;

    prep_kernel<<<2048, 256>>>(Wh, Wx);
    xsplit_kernel<<<2048, 256>>>(x);

    {
        dim3 grid((TT * BB) / 128, GG / 128);   // (1000, 16)
        cudaFuncSetAttribute(xg_hmma, cudaFuncAttributeMaxDynamicSharedMemorySize, SMEM_XG);
        xg_hmma<<<grid, 256, SMEM_XG>>>(bx, bh);
    }

    lstm_hmma<<<NBLK, 512>>>();

    fc_kernel<<<(BB * OO * 32 + 255) / 256, 256>>>(Wfc, bfc, out);
}

// round 13
// speedup vs baseline: 3.3612x; 1.0114x over previous
#include <cuda_runtime.h>
#include <cuda_bf16.h>
#include <math.h>
#include <cstdint>

#define BB 256
#define TT 500
#define II 256
#define HH 512
#define GG 2048
#define OO 100
#define NBLK 128

typedef unsigned long long ull;

// ------------------------- global scratch (no allocs) -----------------------
__device__ float g_xg[(size_t)TT * BB * GG];            // [T][B][4H]
__device__ __nv_bfloat16 g_xs[(size_t)TT * BB * 512];   // [t*B+b][k]: k<256 x1, >=256 x2
__device__ __nv_bfloat16 g_Wxs[GG * 512];               // [n][k]: k<256 Wx1, >=256 Wx2
__device__ uint4 g_Wfrag[32 * 64 * 4 * 32];             // [bn][kt(0-31 W1,32-63 W2)][nt][lane]
__device__ uint4 g_hfrag[2][64 * 16 * 32];              // [buf][kt(0-31 h1,32-63 h2)][mt][lane]
__device__ float g_hfp[BB * HH];                        // fp32 h (for fc)
__device__ unsigned g_barc[4 * 32];                     // 4 group counters, 128B apart

// ------------------------- helpers ------------------------------------------
__device__ __forceinline__ float sigm(float x) { return 1.0f / (1.0f + __expf(-x)); }
__device__ __forceinline__ float tanh_fast(float x) { return 1.0f - 2.0f / (1.0f + __expf(2.0f * x)); }
__device__ __forceinline__ uint32_t smem_u32(const void* p) {
    return (uint32_t)__cvta_generic_to_shared(p);
}
__device__ __forceinline__ void ldsm4(uint32_t& a0, uint32_t& a1, uint32_t& a2, uint32_t& a3,
                                      uint32_t addr) {
    asm volatile("ldmatrix.sync.aligned.m8n8.x4.shared.b16 {%0,%1,%2,%3}, [%4];"
                 : "=r"(a0), "=r"(a1), "=r"(a2), "=r"(a3) : "r"(addr));
}
__device__ __forceinline__ void mma_bf16(float* d, uint32_t a0, uint32_t a1, uint32_t a2,
                                         uint32_t a3, uint32_t b0, uint32_t b1) {
    asm volatile(
        "mma.sync.aligned.m16n8k16.row.col.f32.bf16.bf16.f32 "
        "{%0,%1,%2,%3}, {%4,%5,%6,%7}, {%8,%9}, {%0,%1,%2,%3};"
        : "+f"(d[0]), "+f"(d[1]), "+f"(d[2]), "+f"(d[3])
        : "r"(a0), "r"(a1), "r"(a2), "r"(a3), "r"(b0), "r"(b1));
}
__device__ __forceinline__ uint32_t pack_bf2(float a, float b) {
    __nv_bfloat162 v = __halves2bfloat162(__float2bfloat16(a), __float2bfloat16(b));
    return *reinterpret_cast<uint32_t*>(&v);
}

// ---------------------------------------------------------------------------
// Prep A: split x into g_xs (transposed to [t*B+b] row order)
// ---------------------------------------------------------------------------
__global__ __launch_bounds__(256) void xsplit_kernel(const float* __restrict__ x) {
    const int total = TT * BB * 64;
    const int stride = gridDim.x * blockDim.x;
    for (int idx = blockIdx.x * blockDim.x + threadIdx.x; idx < total; idx += stride) {
        int r = idx >> 6;
        int q = idx & 63;
        int t = r >> 8;
        int b = r & 255;
        float4 v = *(const float4*)(x + ((size_t)b * TT + t) * II + q * 4);
        float r0, r1, r2, r3;
        __nv_bfloat162 h01, h23;
        {
            __nv_bfloat16 p0 = __float2bfloat16(v.x), p1 = __float2bfloat16(v.y);
            __nv_bfloat16 p2 = __float2bfloat16(v.z), p3 = __float2bfloat16(v.w);
            r0 = v.x - __bfloat162float(p0); r1 = v.y - __bfloat162float(p1);
            r2 = v.z - __bfloat162float(p2); r3 = v.w - __bfloat162float(p3);
            h01 = __halves2bfloat162(p0, p1); h23 = __halves2bfloat162(p2, p3);
        }
        __nv_bfloat16* row = g_xs + (size_t)r * 512;
        *(__nv_bfloat162*)(row + q * 4)     = h01;
        *(__nv_bfloat162*)(row + q * 4 + 2) = h23;
        *(__nv_bfloat162*)(row + 256 + q * 4)     = __halves2bfloat162(__float2bfloat16(r0), __float2bfloat16(r1));
        *(__nv_bfloat162*)(row + 256 + q * 4 + 2) = __halves2bfloat162(__float2bfloat16(r2), __float2bfloat16(r3));
    }
}

// ---------------------------------------------------------------------------
// Prep B: Wh -> fragment-major g_Wfrag (unchanged layout, validated R8-R12),
// Wx -> g_Wxs, zero g_hfrag, reset group barriers.
// ---------------------------------------------------------------------------
__global__ __launch_bounds__(256) void prep_kernel(const float* __restrict__ Wh,
                                                   const float* __restrict__ Wx) {
    const int stride = gridDim.x * blockDim.x;
    const int tid0 = blockIdx.x * blockDim.x + threadIdx.x;

    for (int idx = tid0; idx < 32 * 64 * 4 * 32 * 4; idx += stride) {
        int reg = idx & 3, lane = (idx >> 2) & 31, nt = (idx >> 7) & 3;
        int kt = (idx >> 9) & 63, bn = idx >> 15;
        int nl = nt * 16 + (reg & 1) * 8 + (lane >> 2);
        int kk = (kt & 31) * 16 + ((reg >> 1) & 1) * 8 + 2 * (lane & 3);
        int gate = (nl >> 3) & 3;
        int hidl = ((nl >> 5) << 3) + (nl & 7);
        int gcol = (gate << 9) + (bn << 4) + hidl;
        float w0 = Wh[(size_t)gcol * HH + kk];
        float w1 = Wh[(size_t)gcol * HH + kk + 1];
        __nv_bfloat16 h0 = __float2bfloat16(w0), h1 = __float2bfloat16(w1);
        __nv_bfloat162 v;
        if (kt < 32) v = __halves2bfloat162(h0, h1);
        else v = __halves2bfloat162(__float2bfloat16(w0 - __bfloat162float(h0)),
                                    __float2bfloat16(w1 - __bfloat162float(h1)));
        reinterpret_cast<__nv_bfloat162*>(g_Wfrag)[idx] = v;
    }

    for (int idx = tid0; idx < GG * II; idx += stride) {
        int n = idx >> 8, k = idx & 255;
        float w = Wx[idx];
        __nv_bfloat16 w1 = __float2bfloat16(w);
        g_Wxs[(size_t)n * 512 + k] = w1;
        g_Wxs[(size_t)n * 512 + 256 + k] = __float2bfloat16(w - __bfloat162float(w1));
    }

    for (int idx = tid0; idx < 2 * 64 * 16 * 32; idx += stride)
        reinterpret_cast<uint4*>(g_hfrag)[idx] = make_uint4(0, 0, 0, 0);

    if (tid0 < 4 * 32) g_barc[tid0] = 0;
}

// ---------------------------------------------------------------------------
// Kernel 1: xg = x @ Wx^T + bx + bh via HMMA 3-term split (round-9, PASS)
// ---------------------------------------------------------------------------
#define XPAD 72
#define XCHUNK (128 * XPAD * 2)
#define SMEM_XG (4 * XCHUNK)

__global__ __launch_bounds__(256, 1) void xg_hmma(const float* __restrict__ bx,
                                                  const float* __restrict__ bh) {
    extern __shared__ char smem[];
    const int tid = threadIdx.x;
    const int wid = tid >> 5;
    const int lane = tid & 31;
    const int wm = wid & 3;
    const int wn = wid >> 2;
    const int lr = lane & 15;
    const int khalf = lane >> 4;
    const int qp = lane >> 2;
    const int t4 = lane & 3;

    const size_t mBase = (size_t)blockIdx.x * 128;
    const int nBase = blockIdx.y * 128;

    const uint32_t aS[2] = { smem_u32(smem), smem_u32(smem) + XCHUNK };
    const uint32_t bS[2] = { aS[0] + 2 * XCHUNK, aS[0] + 3 * XCHUNK };

    float2 biasv[8];
#pragma unroll
    for (int nb = 0; nb < 8; nb++) {
        int col = nBase + wn * 64 + nb * 8 + 2 * t4;
        biasv[nb] = make_float2(bx[col] + bh[col], bx[col + 1] + bh[col + 1]);
    }

    float acc[2][8][4] = {};
    uint4 pfA[4], pfB[4];

    auto aCol = [](int c) { return ((c >> 2) == 1 ? 256 : 0) + (c & 3) * 64; };
    auto bCol = [](int c) { return ((c >> 2) == 2 ? 256 : 0) + (c & 3) * 64; };

#pragma unroll
    for (int j = 0; j < 4; j++) {
        int u = tid + j * 256;
        int n = u >> 3, q = u & 7;
        pfA[j] = *(const uint4*)(g_xs + (mBase + n) * 512 + aCol(0) + q * 8);
        pfB[j] = *(const uint4*)(g_Wxs + (size_t)(nBase + n) * 512 + bCol(0) + q * 8);
    }
#pragma unroll
    for (int j = 0; j < 4; j++) {
        int u = tid + j * 256;
        int n = u >> 3, q = u & 7;
        *(uint4*)(smem + (size_t)n * (XPAD * 2) + q * 16) = pfA[j];
        *(uint4*)(smem + 2 * XCHUNK + (size_t)n * (XPAD * 2) + q * 16) = pfB[j];
    }
    __syncthreads();

    for (int c = 0; c < 12; c++) {
        const int st = c & 1;
        if (c < 11) {
#pragma unroll
            for (int j = 0; j < 4; j++) {
                int u = tid + j * 256;
                int n = u >> 3, q = u & 7;
                pfA[j] = *(const uint4*)(g_xs + (mBase + n) * 512 + aCol(c + 1) + q * 8);
                pfB[j] = *(const uint4*)(g_Wxs + (size_t)(nBase + n) * 512 + bCol(c + 1) + q * 8);
            }
        }
#pragma unroll
        for (int k16 = 0; k16 < 4; k16++) {
            uint32_t a[2][4];
#pragma unroll
            for (int mi = 0; mi < 2; mi++) {
                uint32_t addr = aS[st] + (uint32_t)(wm * 32 + mi * 16 + lr) * (XPAD * 2)
                                + k16 * 32 + khalf * 16;
                ldsm4(a[mi][0], a[mi][1], a[mi][2], a[mi][3], addr);
            }
#pragma unroll
            for (int p = 0; p < 4; p++) {
                uint32_t b0, b1, b2, b3;
                uint32_t addr = bS[st] + (uint32_t)(wn * 64 + p * 16 + lr) * (XPAD * 2)
                                + k16 * 32 + khalf * 16;
                ldsm4(b0, b1, b2, b3, addr);
#pragma unroll
                for (int mi = 0; mi < 2; mi++) {
                    mma_bf16(acc[mi][2 * p],     a[mi][0], a[mi][1], a[mi][2], a[mi][3], b0, b2);
                    mma_bf16(acc[mi][2 * p + 1], a[mi][0], a[mi][1], a[mi][2], a[mi][3], b1, b3);
                }
            }
        }
        if (c < 11) {
            const int ns = (c + 1) & 1;
#pragma unroll
            for (int j = 0; j < 4; j++) {
                int u = tid + j * 256;
                int n = u >> 3, q = u & 7;
                *(uint4*)(smem + (size_t)ns * XCHUNK + (size_t)n * (XPAD * 2) + q * 16) = pfA[j];
                *(uint4*)(smem + 2 * XCHUNK + (size_t)ns * XCHUNK + (size_t)n * (XPAD * 2) + q * 16) = pfB[j];
            }
            __syncthreads();
        }
    }

#pragma unroll
    for (int mi = 0; mi < 2; mi++) {
#pragma unroll
        for (int rr = 0; rr < 2; rr++) {
            size_t row = mBase + wm * 32 + mi * 16 + qp + rr * 8;
            float* orow = g_xg + row * GG + nBase + wn * 64;
#pragma unroll
            for (int nb = 0; nb < 8; nb++) {
                float2 o = make_float2(acc[mi][nb][2 * rr] + biasv[nb].x,
                                       acc[mi][nb][2 * rr + 1] + biasv[nb].y);
                *(float2*)(orow + nb * 8 + 2 * t4) = o;
            }
        }
    }
}

// ---------------------------------------------------------------------------
// Kernel 2: persistent HMMA LSTM recurrence v5 — 512 threads, 16 warps,
// 6 independent accumulator chains (1 MMA per chain per kt -> 6-way ILP),
// A prefetch queues depth 2 (register-neutral trade vs v4's depth 4).
// Block (bm, bn): 64 batch rows x 64 gate-cols. Warp (wm, wn): M16 x N16.
// Gates via smem tile; pointwise writes h1/h2 straight into frag layout.
// Group barrier per bm (32 blocks).
// ---------------------------------------------------------------------------
#define SGROW 18   // floats per row in gates smem (16 + 2 pad)

__global__ __launch_bounds__(512, 1) void lstm_hmma() {
    __shared__ float sg[4 * 64 * SGROW];   // [gate][row 64][hid 16 (+2)]

    const int tid = threadIdx.x;
    const int lane = tid & 31;
    const int wid = tid >> 5;
    const int wm = wid & 3;
    const int wn = wid >> 2;
    const int qp = lane >> 2;
    const int t4 = lane & 3;

    const int bm = blockIdx.x >> 5;
    const int bn = blockIdx.x & 31;
    const int m0 = bm << 6;
    const int j0 = bn << 4;
    const int mt = bm * 4 + wm;

    const uint4* WfBase = g_Wfrag + (((size_t)bn * 64) * 4 + wn) * 32 + lane;

    const int prow = tid >> 3;
    const int pv = tid & 7;
    const int grow = m0 + prow;
    const int ghid = j0 + 2 * pv;
    const int pmt = bm * 4 + (prow >> 4);
    const int r16 = prow & 15;
    const int comp = (r16 >> 3) + 2 * (pv >> 2);
    const int plane = (r16 & 7) * 4 + (pv & 3);

    unsigned* barp = &g_barc[bm * 32];

    float c0 = 0.f, c1 = 0.f;

    for (int t = 0; t < TT; ++t) {
        const int rb = t & 1;
        const uint4* Af = g_hfrag[rb] + (size_t)mt * 32 + lane;  // + kt*512

        // xg prefetch (DRAM), consumed at pointwise
        float2 xv[4];
#pragma unroll
        for (int g = 0; g < 4; g++)
            xv[g] = __ldcg((const float2*)(g_xg + ((size_t)t * BB + grow) * GG + (g << 9) + ghid));

        // A prefetch queues, depth 2 (h1 + h2)
        uint4 a1q[2], a2q[2];
#pragma unroll
        for (int j = 0; j < 2; j++) {
            a1q[j] = __ldcg(Af + (size_t)j * 512);
            a2q[j] = __ldcg(Af + (size_t)(j + 32) * 512);
        }

        // 6 independent accumulator chains: [term][N8 half]
        float accA[4] = {}, accB[4] = {}, accC[4] = {};
        float accD[4] = {}, accE[4] = {}, accF[4] = {};

#pragma unroll
        for (int kt = 0; kt < 32; kt++) {
            uint4 A1 = a1q[kt & 1], A2 = a2q[kt & 1];
            if (kt < 30) {
                a1q[kt & 1] = __ldcg(Af + (size_t)(kt + 2) * 512);
                a2q[kt & 1] = __ldcg(Af + (size_t)(kt + 34) * 512);
            }
            const uint4* wp = WfBase + (size_t)kt * 128;
            uint4 B1 = wp[0];
            uint4 B2 = wp[32 * 128];

            mma_bf16(accA, A1.x, A1.y, A1.z, A1.w, B1.x, B1.z);   // h1*W1 lo
            mma_bf16(accB, A1.x, A1.y, A1.z, A1.w, B1.y, B1.w);   // h1*W1 hi
            mma_bf16(accC, A1.x, A1.y, A1.z, A1.w, B2.x, B2.z);   // h1*W2 lo
            mma_bf16(accD, A1.x, A1.y, A1.z, A1.w, B2.y, B2.w);   // h1*W2 hi
            mma_bf16(accE, A2.x, A2.y, A2.z, A2.w, B1.x, B1.z);   // h2*W1 lo
            mma_bf16(accF, A2.x, A2.y, A2.z, A2.w, B1.y, B1.w);   // h2*W1 hi
        }

        float acc[2][4];
#pragma unroll
        for (int d = 0; d < 4; d++) {
            acc[0][d] = accA[d] + accC[d] + accE[d];
            acc[1][d] = accB[d] + accD[d] + accF[d];
        }

        // stage gates to smem
#pragma unroll
        for (int p = 0; p < 2; p++) {
            int gate = (2 * wn + p) & 3;
            int hidb = ((wn >> 1) << 3) + 2 * t4;
            float* s0 = &sg[(gate * 64 + wm * 16 + qp) * SGROW + hidb];
            *(float2*)s0 = make_float2(acc[p][0], acc[p][1]);
            float* s1 = &sg[(gate * 64 + wm * 16 + qp + 8) * SGROW + hidb];
            *(float2*)s1 = make_float2(acc[p][2], acc[p][3]);
        }
        __syncthreads();

        // pointwise: 2 cells
        float hv0, hv1;
        {
            float2 gi = *(const float2*)&sg[(0 * 64 + prow) * SGROW + 2 * pv];
            float2 gf = *(const float2*)&sg[(1 * 64 + prow) * SGROW + 2 * pv];
            float2 gg = *(const float2*)&sg[(2 * 64 + prow) * SGROW + 2 * pv];
            float2 go = *(const float2*)&sg[(3 * 64 + prow) * SGROW + 2 * pv];
            float i0 = sigm(gi.x + xv[0].x), i1 = sigm(gi.y + xv[0].y);
            float f0 = sigm(gf.x + xv[1].x), f1 = sigm(gf.y + xv[1].y);
            float g0 = tanh_fast(gg.x + xv[2].x), g1 = tanh_fast(gg.y + xv[2].y);
            float o0 = sigm(go.x + xv[3].x), o1 = sigm(go.y + xv[3].y);
            c0 = c0 * f0 + i0 * g0;
            c1 = c1 * f1 + i1 * g1;
            hv0 = o0 * tanh_fast(c0);
            hv1 = o1 * tanh_fast(c1);
        }

        uint32_t P = pack_bf2(hv0, hv1);
        float q0 = hv0 - __bfloat162float(__float2bfloat16(hv0));
        float q1 = hv1 - __bfloat162float(__float2bfloat16(hv1));
        uint32_t Q = pack_bf2(q0, q1);

        uint4* hb = g_hfrag[rb ^ 1];
        uint32_t* d1 = (uint32_t*)(hb + ((size_t)bn * 16 + pmt) * 32 + plane) + comp;
        *d1 = P;
        uint32_t* d2 = (uint32_t*)(hb + ((size_t)(bn + 32) * 16 + pmt) * 32 + plane) + comp;
        *d2 = Q;

        if (t == TT - 1)
            *(float2*)(g_hfp + (size_t)grow * HH + ghid) = make_float2(hv0, hv1);

        __syncthreads();
        if (tid == 0) {
            __threadfence();
            atomicAdd(barp, 1u);
            const unsigned target = (t + 1) * 32;
            while (*(volatile unsigned*)barp < target) {}
            __threadfence();
        }
        __syncthreads();
    }
}

// ---------------------------------------------------------------------------
__global__ __launch_bounds__(256) void fc_kernel(const float* __restrict__ Wfc,
                                                 const float* __restrict__ bfc,
                                                 float* __restrict__ out) {
    int warp = (blockIdx.x * blockDim.x + threadIdx.x) >> 5;
    int lane = threadIdx.x & 31;
    if (warp >= BB * OO) return;
    int b = warp / OO;
    int o = warp - b * OO;
    const float4* hr = reinterpret_cast<const float4*>(g_hfp + (size_t)b * HH);
    const float4* wr = reinterpret_cast<const float4*>(Wfc + (size_t)o * HH);
    float s = 0.0f;
#pragma unroll
    for (int k = 0; k < 4; k++) {
        float4 h4 = hr[lane + (k << 5)];
        float4 w4 = wr[lane + (k << 5)];
        s += h4.x * w4.x + h4.y * w4.y + h4.z * w4.z + h4.w * w4.w;
    }
#pragma unroll
    for (int off = 16; off; off >>= 1) s += __shfl_xor_sync(0xffffffffu, s, off);
    if (lane == 0) out[warp] = s + bfc[o];
}

// ---------------------------------------------------------------------------
extern "C" void kernel_launch(void* const* d_in, const int* in_sizes, int n_in,
                              void* d_out, int out_size) {
    const float* x   = (const float*)d_in[0];
    const float* Wx  = (const float*)d_in[1];
    const float* bx  = (const float*)d_in[2];
    const float* Wh  = (const float*)d_in[3];
    const float* bh  = (const float*)d_in[4];
    const float* Wfc = (const float*)d_in[5];
    const float* bfc = (const float*)d_in[6];
    float* out = (float*)d_out;

    prep_kernel<<<2048, 256>>>(Wh, Wx);
    xsplit_kernel<<<2048, 256>>>(x);

    {
        dim3 grid((TT * BB) / 128, GG / 128);   // (1000, 16)
        cudaFuncSetAttribute(xg_hmma, cudaFuncAttributeMaxDynamicSharedMemorySize, SMEM_XG);
        xg_hmma<<<grid, 256, SMEM_XG>>>(bx, bh);
    }

    lstm_hmma<<<NBLK, 512>>>();

    fc_kernel<<<(BB * OO * 32 + 255) / 256, 256>>>(Wfc, bfc, out);
}